// round 8
// baseline (speedup 1.0000x reference)
#include <cuda_runtime.h>
#include <math.h>

#define BN 2
#define HH 256
#define WWD 256
#define CC 64
#define PIXB (HH*WWD)
#define NPIX (BN*PIXB)
#define NCHUNK 512

// ---------------- device scratch ----------------
__device__ float g_v [NPIX*CC];
__device__ float g_m1[NPIX*CC];
__device__ float g_m2[NPIX*CC];
__device__ float g_t1[NPIX*CC];
__device__ float g_t2[NPIX*CC];
__device__ float g_vm[NPIX*CC];
__device__ float g_gpart[NCHUNK*4096];
__device__ float g_gpart2[32*4096];
__device__ float g_wfold[BN*4096];
__device__ float g_w2f[4096];
__device__ float g_b2f[64];

__device__ __forceinline__ float sigmf(float x) {
    return 1.0f / (1.0f + __expf(-x));
}
__device__ __forceinline__ float geluf(float v) {
    return 0.5f * v * (1.0f + erff(v * 0.70710678118654752f));
}

// ---------------- Gram partials ----------------
__global__ __launch_bounds__(256) void k_gram_part(const float* __restrict__ x)
{
    __shared__ float sx[8][64];
    int chunk = blockIdx.x;
    int base  = chunk * 256;
    int tid = threadIdx.x;
    int ti = tid >> 4, tj = tid & 15;
    float a00=0,a01=0,a02=0,a03=0, a10=0,a11=0,a12=0,a13=0;
    float a20=0,a21=0,a22=0,a23=0, a30=0,a31=0,a32=0,a33=0;

    for (int pp = 0; pp < 256; pp += 8) {
        __syncthreads();
        int idx = tid * 2;
        int pr = idx >> 6, cc = idx & 63;
        float2 v2 = *(const float2*)&x[(size_t)(base + pp + pr)*CC + cc];
        sx[pr][cc] = v2.x; sx[pr][cc+1] = v2.y;
        __syncthreads();
        #pragma unroll
        for (int p = 0; p < 8; p++) {
            float4 xi = *(const float4*)&sx[p][4*ti];
            float4 xj = *(const float4*)&sx[p][4*tj];
            a00 += xi.x*xj.x; a01 += xi.x*xj.y; a02 += xi.x*xj.z; a03 += xi.x*xj.w;
            a10 += xi.y*xj.x; a11 += xi.y*xj.y; a12 += xi.y*xj.z; a13 += xi.y*xj.w;
            a20 += xi.z*xj.x; a21 += xi.z*xj.y; a22 += xi.z*xj.z; a23 += xi.z*xj.w;
            a30 += xi.w*xj.x; a31 += xi.w*xj.y; a32 += xi.w*xj.z; a33 += xi.w*xj.w;
        }
    }
    float* dst = &g_gpart[(size_t)chunk*4096];
    int r = 4*ti, c = 4*tj;
    dst[(r+0)*64+c+0]=a00; dst[(r+0)*64+c+1]=a01; dst[(r+0)*64+c+2]=a02; dst[(r+0)*64+c+3]=a03;
    dst[(r+1)*64+c+0]=a10; dst[(r+1)*64+c+1]=a11; dst[(r+1)*64+c+2]=a12; dst[(r+1)*64+c+3]=a13;
    dst[(r+2)*64+c+0]=a20; dst[(r+2)*64+c+1]=a21; dst[(r+2)*64+c+2]=a22; dst[(r+2)*64+c+3]=a23;
    dst[(r+3)*64+c+0]=a30; dst[(r+3)*64+c+1]=a31; dst[(r+3)*64+c+2]=a32; dst[(r+3)*64+c+3]=a33;
}

__global__ void k_gram_red1()
{
    int e = blockIdx.x*blockDim.x + threadIdx.x;
    if (e >= 32*4096) return;
    int part = e >> 12, i = e & 4095;
    float s = 0.f;
    #pragma unroll
    for (int c = 0; c < 16; c++)
        s += g_gpart[(size_t)(part*16 + c)*4096 + i];
    g_gpart2[e] = s;
}

// ---------------- fold W2*W1 (16 blocks), b2f = W2 b1 + b2 ----------------
__global__ __launch_bounds__(256) void k_fold16(const float* __restrict__ W1,
                                                const float* __restrict__ b1,
                                                const float* __restrict__ W2,
                                                const float* __restrict__ b2)
{
    __shared__ float sW1[4096];
    int tid = threadIdx.x;
    for (int t = tid; t < 4096; t += 256) sW1[t] = W1[t];
    __syncthreads();
    int t = blockIdx.x*256 + tid;          // one output each
    int o = t >> 6, c = t & 63;
    float s = 0.f;
    #pragma unroll 8
    for (int i = 0; i < 64; i++) s += W2[o*64+i] * sW1[i*64+c];
    g_w2f[t] = s;
    if (blockIdx.x == 0 && tid < 64) {
        float sb = b2[tid];
        #pragma unroll 8
        for (int i = 0; i < 64; i++) sb += W2[tid*64+i] * b1[i];
        g_b2f[tid] = sb;
    }
}

// ---------------- tiny solve (all-smem), gram reduce folded in ----------------
__global__ __launch_bounds__(256) void k_small3(const float* __restrict__ Wq,
                                                const float* __restrict__ Wk,
                                                const float* __restrict__ Wp,
                                                const float* __restrict__ rs)
{
    extern __shared__ float dyn[];
    float* sG   = dyn;
    float* sGq  = dyn + 4096;
    float* sW   = dyn + 8192;
    float* sLog = dyn + 12288;
    float* sNq  = dyn + 13312;
    float* sNk  = dyn + 13376;
    float* sPart= dyn + 13440;
    int b = blockIdx.x;
    int tid = threadIdx.x;

    for (int t = tid; t < 4096; t += 256) {
        float s = 0.f;
        #pragma unroll
        for (int c = 0; c < 16; c++)
            s += g_gpart2[(size_t)(b*16 + c)*4096 + t];
        sG[t] = s;
        sW[t] = Wq[t];
    }
    __syncthreads();
    for (int t = tid; t < 4096; t += 256) {
        int c = t >> 6, o = t & 63;
        float s = 0.f;
        #pragma unroll 8
        for (int i = 0; i < 64; i++) s += sG[c*64+i] * sW[o*64+i];
        sGq[t] = s;
    }
    __syncthreads();
    if (tid < 64) {
        int o = tid;
        float qq = 0.f;
        #pragma unroll 8
        for (int c = 0; c < 64; c++) qq += sW[o*64+c] * sGq[c*64+o];
        sNq[o] = fmaxf(sqrtf(fmaxf(qq, 0.f)), 1e-12f);
    }
    __syncthreads();
    for (int t = tid; t < 4096; t += 256) sW[t] = Wk[t];
    __syncthreads();
    {
        int o = tid >> 2, part = tid & 3;
        float kp = 0.f;
        for (int c = part*16; c < part*16 + 16; c++) {
            float gk = 0.f;
            #pragma unroll 8
            for (int i = 0; i < 64; i++) gk += sG[c*64+i] * sW[o*64+i];
            kp += sW[o*64+c] * gk;
        }
        sPart[tid] = kp;
    }
    __syncthreads();
    if (tid < 64) {
        float kk = sPart[4*tid] + sPart[4*tid+1] + sPart[4*tid+2] + sPart[4*tid+3];
        sNk[tid] = fmaxf(sqrtf(fmaxf(kk, 0.f)), 1e-12f);
    }
    __syncthreads();
    for (int t = tid; t < 1024; t += 256) {
        int h = t >> 8, d = (t >> 4) & 15, e = t & 15;
        int rk = h*16 + d, rq = h*16 + e;
        float s = 0.f;
        #pragma unroll 8
        for (int c = 0; c < 64; c++) s += sW[rk*64+c] * sGq[c*64+rq];
        sLog[t] = s / (sNk[rk] * sNq[rq]) * rs[h];
    }
    __syncthreads();
    if (tid < 64) {
        float* row = &sLog[tid*16];
        float m = row[0];
        for (int e = 1; e < 16; e++) m = fmaxf(m, row[e]);
        float sum = 0.f;
        for (int e = 0; e < 16; e++) { float ev = expf(row[e]-m); row[e] = ev; sum += ev; }
        float inv = 1.f / sum;
        for (int e = 0; e < 16; e++) row[e] *= inv;
    }
    __syncthreads();
    for (int t = tid; t < 4096; t += 256) sW[t] = Wp[t];
    __syncthreads();
    for (int t = tid; t < 4096; t += 256) {
        int o = t >> 6, j = t & 63, hj = j >> 4, ej = j & 15;
        float s = 0.f;
        #pragma unroll
        for (int d = 0; d < 16; d++)
            s += sW[o*64 + hj*16 + d] * sLog[(hj*16 + d)*16 + ej];
        g_wfold[b*4096 + t] = s;
    }
}

// ---------------- matvec, one W-row per lane ----------------
__global__ __launch_bounds__(256) void k_mv_b(const float* __restrict__ in,
                                              const float* __restrict__ Wg,
                                              const float* __restrict__ bias,
                                              const float* __restrict__ add,
                                              float* __restrict__ out,
                                              int wsel)
{
    __shared__ float4 sx4[2048];
    float* sx = (float*)sx4;
    int tid = threadIdx.x, lane = tid & 31, wid = tid >> 5;
    int row = (wid >> 2)*32 + lane;
    const float* W = Wg + (wsel ? (int)(blockIdx.x >> 9) * 4096 : 0);

    for (int t = tid; t < 4096; t += 256) sx[(t >> 6)*68 + (t & 63)] = W[t];
    __syncthreads();
    float w[64];
    #pragma unroll
    for (int k = 0; k < 16; k++) {
        float4 a = *(const float4*)&sx[row*68 + 4*k];
        w[4*k+0]=a.x; w[4*k+1]=a.y; w[4*k+2]=a.z; w[4*k+3]=a.w;
    }
    float bb = bias ? bias[row] : 0.f;
    __syncthreads();

    size_t pbase = (size_t)blockIdx.x * 128;
    const float4* in4 = (const float4*)in + pbase*16;
    #pragma unroll
    for (int j = 0; j < 8; j++) sx4[tid + 256*j] = in4[tid + 256*j];
    __syncthreads();

    int pw = (wid & 3) * 32;
    #pragma unroll 2
    for (int q = 0; q < 8; q++) {
        int p0 = pw + q*4;
        float a0 = bb, a1 = bb, a2 = bb, a3 = bb;
        #pragma unroll
        for (int k4 = 0; k4 < 16; k4++) {
            float4 x0 = *(const float4*)&sx[(p0+0)*64 + 4*k4];
            float4 x1 = *(const float4*)&sx[(p0+1)*64 + 4*k4];
            float4 x2 = *(const float4*)&sx[(p0+2)*64 + 4*k4];
            float4 x3 = *(const float4*)&sx[(p0+3)*64 + 4*k4];
            a0 = fmaf(w[4*k4+0], x0.x, a0); a0 = fmaf(w[4*k4+1], x0.y, a0);
            a0 = fmaf(w[4*k4+2], x0.z, a0); a0 = fmaf(w[4*k4+3], x0.w, a0);
            a1 = fmaf(w[4*k4+0], x1.x, a1); a1 = fmaf(w[4*k4+1], x1.y, a1);
            a1 = fmaf(w[4*k4+2], x1.z, a1); a1 = fmaf(w[4*k4+3], x1.w, a1);
            a2 = fmaf(w[4*k4+0], x2.x, a2); a2 = fmaf(w[4*k4+1], x2.y, a2);
            a2 = fmaf(w[4*k4+2], x2.z, a2); a2 = fmaf(w[4*k4+3], x2.w, a2);
            a3 = fmaf(w[4*k4+0], x3.x, a3); a3 = fmaf(w[4*k4+1], x3.y, a3);
            a3 = fmaf(w[4*k4+2], x3.z, a3); a3 = fmaf(w[4*k4+3], x3.w, a3);
        }
        size_t o0 = (pbase + p0)*64 + row;
        if (add) {
            a0 += add[o0]; a1 += add[o0+64]; a2 += add[o0+128]; a3 += add[o0+192];
        }
        out[o0]     = a0;
        out[o0+64]  = a1;
        out[o0+128] = a2;
        out[o0+192] = a3;
    }
}

// ---------------- dwconv, 8-pixel strips ----------------
__global__ __launch_bounds__(256) void k_pe1_s(const float* __restrict__ x,
                                               const float* __restrict__ w)
{
    __shared__ float sw[9*CC];
    for (int t = threadIdx.x; t < 9*CC; t += 256) { int c = t/9, k = t%9; sw[k*CC+c] = w[t]; }
    __syncthreads();
    int g = threadIdx.x & 15, strip = threadIdx.x >> 4;
    int pbase = blockIdx.x*128 + strip*8;
    int b = pbase >> 16, s = pbase & 65535, y = s >> 8, x0 = s & 255;
    const float4* x4 = (const float4*)x;
    const float4* sw4 = (const float4*)sw;
    float4 acc[8];
    #pragma unroll
    for (int p = 0; p < 8; p++) acc[p] = make_float4(0.f,0.f,0.f,0.f);
    size_t bb = (size_t)(b << 16);
    #pragma unroll
    for (int ky = 0; ky < 3; ky++) {
        int yy = y + ky - 1; if (yy < 0 || yy >= HH) continue;
        #pragma unroll
        for (int c = -1; c <= 8; c++) {
            int xc = x0 + c; if (xc < 0 || xc >= WWD) continue;
            float4 v = x4[(bb + (yy<<8) + xc)*16 + g];
            #pragma unroll
            for (int p = 0; p < 8; p++) {
                int kx = c - p + 1; if (kx < 0 || kx > 2) continue;
                float4 wv = sw4[(ky*3+kx)*16 + g];
                acc[p].x = fmaf(wv.x, v.x, acc[p].x); acc[p].y = fmaf(wv.y, v.y, acc[p].y);
                acc[p].z = fmaf(wv.z, v.z, acc[p].z); acc[p].w = fmaf(wv.w, v.w, acc[p].w);
            }
        }
    }
    float4* t14 = (float4*)g_t1;
    #pragma unroll
    for (int p = 0; p < 8; p++) {
        float4 r;
        r.x = geluf(acc[p].x); r.y = geluf(acc[p].y);
        r.z = geluf(acc[p].z); r.w = geluf(acc[p].w);
        t14[(size_t)(pbase+p)*16 + g] = r;
    }
}

__global__ __launch_bounds__(256) void k_pe2_s(const float* __restrict__ w)
{
    __shared__ float sw[9*CC];
    for (int t = threadIdx.x; t < 9*CC; t += 256) { int c = t/9, k = t%9; sw[k*CC+c] = w[t]; }
    __syncthreads();
    int g = threadIdx.x & 15, strip = threadIdx.x >> 4;
    int pbase = blockIdx.x*128 + strip*8;
    int b = pbase >> 16, s = pbase & 65535, y = s >> 8, x0 = s & 255;
    const float4* t14 = (const float4*)g_t1;
    const float4* sw4 = (const float4*)sw;
    float4 acc[8];
    #pragma unroll
    for (int p = 0; p < 8; p++) acc[p] = make_float4(0.f,0.f,0.f,0.f);
    size_t bb = (size_t)(b << 16);
    #pragma unroll
    for (int ky = 0; ky < 3; ky++) {
        int yy = y + ky - 1; if (yy < 0 || yy >= HH) continue;
        #pragma unroll
        for (int c = -1; c <= 8; c++) {
            int xc = x0 + c; if (xc < 0 || xc >= WWD) continue;
            float4 v = t14[(bb + (yy<<8) + xc)*16 + g];
            #pragma unroll
            for (int p = 0; p < 8; p++) {
                int kx = c - p + 1; if (kx < 0 || kx > 2) continue;
                float4 wv = sw4[(ky*3+kx)*16 + g];
                acc[p].x = fmaf(wv.x, v.x, acc[p].x); acc[p].y = fmaf(wv.y, v.y, acc[p].y);
                acc[p].z = fmaf(wv.z, v.z, acc[p].z); acc[p].w = fmaf(wv.w, v.w, acc[p].w);
            }
        }
    }
    float4* t24 = (float4*)g_t2;
    #pragma unroll
    for (int p = 0; p < 8; p++) t24[(size_t)(pbase+p)*16 + g] = acc[p];
}

__global__ __launch_bounds__(256) void k_ma_s(const float* __restrict__ dw,
                                              const float* __restrict__ dwb)
{
    __shared__ float sdw[25*CC];
    __shared__ float sdb[CC];
    for (int t = threadIdx.x; t < 25*CC; t += 256) { int c = t/25, k = t%25; sdw[k*CC+c] = dw[t]; }
    for (int t = threadIdx.x; t < CC; t += 256) sdb[t] = dwb[t];
    __syncthreads();
    int g = threadIdx.x & 15, strip = threadIdx.x >> 4;
    int pbase = blockIdx.x*128 + strip*8;
    int b = pbase >> 16, s = pbase & 65535, y = s >> 8, x0 = s & 255;
    const float4* m24 = (const float4*)g_m2;
    const float4* sdw4 = (const float4*)sdw;
    float4 bias4 = ((const float4*)sdb)[g];
    float4 acc[8];
    #pragma unroll
    for (int p = 0; p < 8; p++) acc[p] = bias4;
    size_t bb = (size_t)(b << 16);
    #pragma unroll
    for (int ky = 0; ky < 5; ky++) {
        int yy = y + ky - 2; if (yy < 0 || yy >= HH) continue;
        #pragma unroll
        for (int c = -2; c <= 9; c++) {
            int xc = x0 + c; if (xc < 0 || xc >= WWD) continue;
            float4 v = m24[(bb + (yy<<8) + xc)*16 + g];
            #pragma unroll
            for (int p = 0; p < 8; p++) {
                int kx = c - p + 2; if (kx < 0 || kx > 4) continue;
                float4 wv = sdw4[(ky*5+kx)*16 + g];
                acc[p].x = fmaf(wv.x, v.x, acc[p].x); acc[p].y = fmaf(wv.y, v.y, acc[p].y);
                acc[p].z = fmaf(wv.z, v.z, acc[p].z); acc[p].w = fmaf(wv.w, v.w, acc[p].w);
            }
        }
    }
    const float4* m14 = (const float4*)g_m1;
    const float4* v4  = (const float4*)g_v;
    float4* vm4 = (float4*)g_vm;
    #pragma unroll
    for (int p = 0; p < 8; p++) {
        size_t idx = (size_t)(pbase+p)*16 + g;
        float4 m1v = m14[idx], vv = v4[idx];
        float4 r;
        r.x = vv.x * (m1v.x * (1.f + sigmf(acc[p].x)));
        r.y = vv.y * (m1v.y * (1.f + sigmf(acc[p].y)));
        r.z = vv.z * (m1v.z * (1.f + sigmf(acc[p].z)));
        r.w = vv.w * (m1v.w * (1.f + sigmf(acc[p].w)));
        vm4[idx] = r;
    }
}

// ---------------- launcher: fork/join across 4 streams ----------------
extern "C" void kernel_launch(void* const* d_in, const int* in_sizes, int n_in,
                              void* d_out, int out_size)
{
    const float* x_in   = (const float*)d_in[0];
    const float* mask   = (const float*)d_in[1];
    const float* Wq     = (const float*)d_in[2];
    const float* Wk     = (const float*)d_in[3];
    const float* Wv     = (const float*)d_in[4];
    const float* rescale= (const float*)d_in[5];
    const float* Wp     = (const float*)d_in[6];
    const float* bp     = (const float*)d_in[7];
    const float* mm_w1  = (const float*)d_in[8];
    const float* mm_b1  = (const float*)d_in[9];
    const float* mm_w2  = (const float*)d_in[10];
    const float* mm_b2  = (const float*)d_in[11];
    const float* mm_dw  = (const float*)d_in[12];
    const float* mm_dwb = (const float*)d_in[13];
    const float* pe_w1  = (const float*)d_in[14];
    const float* pe_w2  = (const float*)d_in[15];
    float* out = (float*)d_out;

    float *pm1, *pm2, *pv, *pvm, *pt2, *pwf, *pw2f, *pb2f;
    cudaGetSymbolAddress((void**)&pm1,  g_m1);
    cudaGetSymbolAddress((void**)&pm2,  g_m2);
    cudaGetSymbolAddress((void**)&pv,   g_v);
    cudaGetSymbolAddress((void**)&pvm,  g_vm);
    cudaGetSymbolAddress((void**)&pt2,  g_t2);
    cudaGetSymbolAddress((void**)&pwf,  g_wfold);
    cudaGetSymbolAddress((void**)&pw2f, g_w2f);
    cudaGetSymbolAddress((void**)&pb2f, g_b2f);

    const int SM3_BYTES = (4096*3 + 1024 + 64 + 64 + 256) * 4;

    static cudaStream_t s1 = nullptr, s2 = nullptr, s3 = nullptr;
    static cudaEvent_t evRoot = nullptr, evV = nullptr, evM = nullptr, evP = nullptr, evF = nullptr;
    static int init_done = 0;
    if (!init_done) {
        cudaFuncSetAttribute(k_small3, cudaFuncAttributeMaxDynamicSharedMemorySize, SM3_BYTES);
        cudaStreamCreateWithFlags(&s1, cudaStreamNonBlocking);
        cudaStreamCreateWithFlags(&s2, cudaStreamNonBlocking);
        cudaStreamCreateWithFlags(&s3, cudaStreamNonBlocking);
        cudaEventCreateWithFlags(&evRoot, cudaEventDisableTiming);
        cudaEventCreateWithFlags(&evV,    cudaEventDisableTiming);
        cudaEventCreateWithFlags(&evM,    cudaEventDisableTiming);
        cudaEventCreateWithFlags(&evP,    cudaEventDisableTiming);
        cudaEventCreateWithFlags(&evF,    cudaEventDisableTiming);
        init_done = 1;
    }

    bool multi = (s1 && s2 && s3 && evRoot && evV && evM && evP && evF);

    if (multi) {
        cudaEventRecord(evRoot, 0);
        cudaStreamWaitEvent(s1, evRoot, 0);
        cudaStreamWaitEvent(s2, evRoot, 0);
        cudaStreamWaitEvent(s3, evRoot, 0);

        // s3: fold (off critical path)
        k_fold16<<<16, 256, 0, s3>>>(mm_w1, mm_b1, mm_w2, mm_b2);
        cudaEventRecord(evF, s3);

        // stream 0: gram chain
        k_gram_part<<<NCHUNK, 256>>>(x_in);
        k_gram_red1<<<(32*4096)/256, 256>>>();
        k_small3<<<BN, 256, SM3_BYTES>>>(Wq, Wk, Wp, rescale);

        // s1: mask path — m1 first (no fold dependency), then m2 (waits fold)
        k_mv_b<<<NPIX/128, 256, 0, s1>>>(mask, mm_w1, mm_b1, nullptr, pm1, 0);
        cudaStreamWaitEvent(s1, evF, 0);
        k_mv_b<<<NPIX/128, 256, 0, s1>>>(mask, pw2f, pb2f, nullptr, pm2, 0);

        // s2: x path
        k_mv_b<<<NPIX/128, 256, 0, s2>>>(x_in, Wv, nullptr, nullptr, pv, 0);
        cudaEventRecord(evV, s2);
        k_pe1_s<<<NPIX/128, 256, 0, s2>>>(x_in, pe_w1);
        k_pe2_s<<<NPIX/128, 256, 0, s2>>>(pe_w2);
        cudaEventRecord(evP, s2);

        // ma on s1 (needs m1, m2 s1-ordered; v via evV)
        cudaStreamWaitEvent(s1, evV, 0);
        k_ma_s<<<NPIX/128, 256, 0, s1>>>(mm_dw, mm_dwb);
        cudaEventRecord(evM, s1);

        // join
        cudaStreamWaitEvent(0, evM, 0);
        cudaStreamWaitEvent(0, evP, 0);
        k_mv_b<<<NPIX/128, 256>>>(pvm, pwf, bp, pt2, out, 1);
    } else {
        k_fold16<<<16, 256>>>(mm_w1, mm_b1, mm_w2, mm_b2);
        k_gram_part<<<NCHUNK, 256>>>(x_in);
        k_gram_red1<<<(32*4096)/256, 256>>>();
        k_small3<<<BN, 256, SM3_BYTES>>>(Wq, Wk, Wp, rescale);
        k_mv_b<<<NPIX/128, 256>>>(mask, mm_w1, mm_b1, nullptr, pm1, 0);
        k_mv_b<<<NPIX/128, 256>>>(mask, pw2f, pb2f, nullptr, pm2, 0);
        k_mv_b<<<NPIX/128, 256>>>(x_in, Wv, nullptr, nullptr, pv, 0);
        k_pe1_s<<<NPIX/128, 256>>>(x_in, pe_w1);
        k_pe2_s<<<NPIX/128, 256>>>(pe_w2);
        k_ma_s <<<NPIX/128, 256>>>(mm_dw, mm_dwb);
        k_mv_b<<<NPIX/128, 256>>>(pvm, pwf, bp, pt2, out, 1);
    }
}

// round 9
// speedup vs baseline: 1.2354x; 1.2354x over previous
#include <cuda_runtime.h>
#include <math.h>

#define BN 2
#define HH 256
#define WWD 256
#define CC 64
#define PIXB (HH*WWD)
#define NPIX (BN*PIXB)
#define NCHUNK 512

// ---------------- device scratch ----------------
__device__ float g_v [NPIX*CC];
__device__ float g_m1[NPIX*CC];
__device__ float g_m2[NPIX*CC];
__device__ float g_t1[NPIX*CC];
__device__ float g_t2[NPIX*CC];
__device__ float g_vm[NPIX*CC];
__device__ float g_gpart[NCHUNK*4096];
__device__ float g_gpart2[32*4096];
__device__ float g_wfold[BN*4096];
__device__ float g_w2f[4096];
__device__ float g_b2f[64];

__device__ __forceinline__ float sigmf(float x) {
    return 1.0f / (1.0f + __expf(-x));
}
__device__ __forceinline__ float geluf(float v) {
    return 0.5f * v * (1.0f + erff(v * 0.70710678118654752f));
}

// ---------------- Gram partials ----------------
__global__ __launch_bounds__(256) void k_gram_part(const float* __restrict__ x)
{
    __shared__ float sx[8][64];
    int chunk = blockIdx.x;
    int base  = chunk * 256;
    int tid = threadIdx.x;
    int ti = tid >> 4, tj = tid & 15;
    float a00=0,a01=0,a02=0,a03=0, a10=0,a11=0,a12=0,a13=0;
    float a20=0,a21=0,a22=0,a23=0, a30=0,a31=0,a32=0,a33=0;

    for (int pp = 0; pp < 256; pp += 8) {
        __syncthreads();
        int idx = tid * 2;
        int pr = idx >> 6, cc = idx & 63;
        float2 v2 = *(const float2*)&x[(size_t)(base + pp + pr)*CC + cc];
        sx[pr][cc] = v2.x; sx[pr][cc+1] = v2.y;
        __syncthreads();
        #pragma unroll
        for (int p = 0; p < 8; p++) {
            float4 xi = *(const float4*)&sx[p][4*ti];
            float4 xj = *(const float4*)&sx[p][4*tj];
            a00 += xi.x*xj.x; a01 += xi.x*xj.y; a02 += xi.x*xj.z; a03 += xi.x*xj.w;
            a10 += xi.y*xj.x; a11 += xi.y*xj.y; a12 += xi.y*xj.z; a13 += xi.y*xj.w;
            a20 += xi.z*xj.x; a21 += xi.z*xj.y; a22 += xi.z*xj.z; a23 += xi.z*xj.w;
            a30 += xi.w*xj.x; a31 += xi.w*xj.y; a32 += xi.w*xj.z; a33 += xi.w*xj.w;
        }
    }
    float* dst = &g_gpart[(size_t)chunk*4096];
    int r = 4*ti, c = 4*tj;
    dst[(r+0)*64+c+0]=a00; dst[(r+0)*64+c+1]=a01; dst[(r+0)*64+c+2]=a02; dst[(r+0)*64+c+3]=a03;
    dst[(r+1)*64+c+0]=a10; dst[(r+1)*64+c+1]=a11; dst[(r+1)*64+c+2]=a12; dst[(r+1)*64+c+3]=a13;
    dst[(r+2)*64+c+0]=a20; dst[(r+2)*64+c+1]=a21; dst[(r+2)*64+c+2]=a22; dst[(r+2)*64+c+3]=a23;
    dst[(r+3)*64+c+0]=a30; dst[(r+3)*64+c+1]=a31; dst[(r+3)*64+c+2]=a32; dst[(r+3)*64+c+3]=a33;
}

__global__ void k_gram_red1()
{
    int e = blockIdx.x*blockDim.x + threadIdx.x;
    if (e >= 32*4096) return;
    int part = e >> 12, i = e & 4095;
    float s = 0.f;
    #pragma unroll
    for (int c = 0; c < 16; c++)
        s += g_gpart[(size_t)(part*16 + c)*4096 + i];
    g_gpart2[e] = s;
}

// ---------------- fold W2*W1 (16 blocks), b2f = W2 b1 + b2 ----------------
__global__ __launch_bounds__(256) void k_fold16(const float* __restrict__ W1,
                                                const float* __restrict__ b1,
                                                const float* __restrict__ W2,
                                                const float* __restrict__ b2)
{
    __shared__ float sW1[4096];
    int tid = threadIdx.x;
    for (int t = tid; t < 4096; t += 256) sW1[t] = W1[t];
    __syncthreads();
    int t = blockIdx.x*256 + tid;
    int o = t >> 6, c = t & 63;
    float s = 0.f;
    #pragma unroll 8
    for (int i = 0; i < 64; i++) s += W2[o*64+i] * sW1[i*64+c];
    g_w2f[t] = s;
    if (blockIdx.x == 0 && tid < 64) {
        float sb = b2[tid];
        #pragma unroll 8
        for (int i = 0; i < 64; i++) sb += W2[tid*64+i] * b1[i];
        g_b2f[tid] = sb;
    }
}

// ---------------- tiny solve, bank-conflict-free (stride-65 panes) ----------------
#define SP 65
__global__ __launch_bounds__(256) void k_small4(const float* __restrict__ Wq,
                                                const float* __restrict__ Wk,
                                                const float* __restrict__ Wp,
                                                const float* __restrict__ rs)
{
    extern __shared__ float dyn[];
    float* sG   = dyn;            // 64*65 = 4160
    float* sGq  = dyn + 4160;     // 4160
    float* sW   = dyn + 8320;     // 4160
    float* sLog = dyn + 12480;    // 1024
    float* sNq  = dyn + 13504;    // 64
    float* sNk  = dyn + 13568;    // 64
    float* sPart= dyn + 13632;    // 256
    int b = blockIdx.x;
    int tid = threadIdx.x;

    // final gram reduce (deterministic), padded stores
    for (int t = tid; t < 4096; t += 256) {
        float s = 0.f;
        #pragma unroll
        for (int c = 0; c < 16; c++)
            s += g_gpart2[(size_t)(b*16 + c)*4096 + t];
        sG[(t >> 6)*SP + (t & 63)] = s;
        sW[(t >> 6)*SP + (t & 63)] = Wq[t];
    }
    __syncthreads();
    // Gq[c][o] = (G Wq^T)[c][o]
    for (int t = tid; t < 4096; t += 256) {
        int c = t >> 6, o = t & 63;
        float s = 0.f;
        #pragma unroll 8
        for (int i = 0; i < 64; i++) s += sG[c*SP+i] * sW[o*SP+i];
        sGq[c*SP+o] = s;
    }
    __syncthreads();
    if (tid < 64) {
        int o = tid;
        float qq = 0.f;
        #pragma unroll 8
        for (int c = 0; c < 64; c++) qq += sW[o*SP+c] * sGq[c*SP+o];
        sNq[o] = fmaxf(sqrtf(fmaxf(qq, 0.f)), 1e-12f);
    }
    __syncthreads();
    for (int t = tid; t < 4096; t += 256) sW[(t >> 6)*SP + (t & 63)] = Wk[t];
    __syncthreads();
    {
        int o = tid >> 2, part = tid & 3;
        float kp = 0.f;
        for (int c = part*16; c < part*16 + 16; c++) {
            float gk = 0.f;
            #pragma unroll 8
            for (int i = 0; i < 64; i++) gk += sG[c*SP+i] * sW[o*SP+i];
            kp += sW[o*SP+c] * gk;
        }
        sPart[tid] = kp;
    }
    __syncthreads();
    if (tid < 64) {
        float kk = sPart[4*tid] + sPart[4*tid+1] + sPart[4*tid+2] + sPart[4*tid+3];
        sNk[tid] = fmaxf(sqrtf(fmaxf(kk, 0.f)), 1e-12f);
    }
    __syncthreads();
    for (int t = tid; t < 1024; t += 256) {
        int h = t >> 8, d = (t >> 4) & 15, e = t & 15;
        int rk = h*16 + d, rq = h*16 + e;
        float s = 0.f;
        #pragma unroll 8
        for (int c = 0; c < 64; c++) s += sW[rk*SP+c] * sGq[c*SP+rq];
        sLog[t] = s / (sNk[rk] * sNq[rq]) * rs[h];
    }
    __syncthreads();
    if (tid < 64) {
        float* row = &sLog[tid*16];
        float m = row[0];
        for (int e = 1; e < 16; e++) m = fmaxf(m, row[e]);
        float sum = 0.f;
        for (int e = 0; e < 16; e++) { float ev = expf(row[e]-m); row[e] = ev; sum += ev; }
        float inv = 1.f / sum;
        for (int e = 0; e < 16; e++) row[e] *= inv;
    }
    __syncthreads();
    for (int t = tid; t < 4096; t += 256) sW[(t >> 6)*SP + (t & 63)] = Wp[t];
    __syncthreads();
    for (int t = tid; t < 4096; t += 256) {
        int o = t >> 6, j = t & 63, hj = j >> 4, ej = j & 15;
        float s = 0.f;
        #pragma unroll
        for (int d = 0; d < 16; d++)
            s += sW[o*SP + hj*16 + d] * sLog[(hj*16 + d)*16 + ej];
        g_wfold[b*4096 + t] = s;
    }
}

// ---------------- matvec, one W-row per lane ----------------
__global__ __launch_bounds__(256) void k_mv_b(const float* __restrict__ in,
                                              const float* __restrict__ Wg,
                                              const float* __restrict__ bias,
                                              const float* __restrict__ add,
                                              float* __restrict__ out,
                                              int wsel)
{
    __shared__ float4 sx4[2048];
    float* sx = (float*)sx4;
    int tid = threadIdx.x, lane = tid & 31, wid = tid >> 5;
    int row = (wid >> 2)*32 + lane;
    const float* W = Wg + (wsel ? (int)(blockIdx.x >> 9) * 4096 : 0);

    for (int t = tid; t < 4096; t += 256) sx[(t >> 6)*68 + (t & 63)] = W[t];
    __syncthreads();
    float w[64];
    #pragma unroll
    for (int k = 0; k < 16; k++) {
        float4 a = *(const float4*)&sx[row*68 + 4*k];
        w[4*k+0]=a.x; w[4*k+1]=a.y; w[4*k+2]=a.z; w[4*k+3]=a.w;
    }
    float bb = bias ? bias[row] : 0.f;
    __syncthreads();

    size_t pbase = (size_t)blockIdx.x * 128;
    const float4* in4 = (const float4*)in + pbase*16;
    #pragma unroll
    for (int j = 0; j < 8; j++) sx4[tid + 256*j] = in4[tid + 256*j];
    __syncthreads();

    int pw = (wid & 3) * 32;
    #pragma unroll 2
    for (int q = 0; q < 8; q++) {
        int p0 = pw + q*4;
        float a0 = bb, a1 = bb, a2 = bb, a3 = bb;
        #pragma unroll
        for (int k4 = 0; k4 < 16; k4++) {
            float4 x0 = *(const float4*)&sx[(p0+0)*64 + 4*k4];
            float4 x1 = *(const float4*)&sx[(p0+1)*64 + 4*k4];
            float4 x2 = *(const float4*)&sx[(p0+2)*64 + 4*k4];
            float4 x3 = *(const float4*)&sx[(p0+3)*64 + 4*k4];
            a0 = fmaf(w[4*k4+0], x0.x, a0); a0 = fmaf(w[4*k4+1], x0.y, a0);
            a0 = fmaf(w[4*k4+2], x0.z, a0); a0 = fmaf(w[4*k4+3], x0.w, a0);
            a1 = fmaf(w[4*k4+0], x1.x, a1); a1 = fmaf(w[4*k4+1], x1.y, a1);
            a1 = fmaf(w[4*k4+2], x1.z, a1); a1 = fmaf(w[4*k4+3], x1.w, a1);
            a2 = fmaf(w[4*k4+0], x2.x, a2); a2 = fmaf(w[4*k4+1], x2.y, a2);
            a2 = fmaf(w[4*k4+2], x2.z, a2); a2 = fmaf(w[4*k4+3], x2.w, a2);
            a3 = fmaf(w[4*k4+0], x3.x, a3); a3 = fmaf(w[4*k4+1], x3.y, a3);
            a3 = fmaf(w[4*k4+2], x3.z, a3); a3 = fmaf(w[4*k4+3], x3.w, a3);
        }
        size_t o0 = (pbase + p0)*64 + row;
        if (add) {
            a0 += add[o0]; a1 += add[o0+64]; a2 += add[o0+128]; a3 += add[o0+192];
        }
        out[o0]     = a0;
        out[o0+64]  = a1;
        out[o0+128] = a2;
        out[o0+192] = a3;
    }
}

// ---------------- dwconv, 4-pixel strips (R7 proven versions) ----------------
__global__ __launch_bounds__(256) void k_pe1_s(const float* __restrict__ x,
                                               const float* __restrict__ w)
{
    __shared__ float sw[9*CC];
    for (int t = threadIdx.x; t < 9*CC; t += 256) { int c = t/9, k = t%9; sw[k*CC+c] = w[t]; }
    __syncthreads();
    int g = threadIdx.x & 15, strip = threadIdx.x >> 4;
    int pbase = blockIdx.x*64 + strip*4;
    int b = pbase >> 16, s = pbase & 65535, y = s >> 8, x0 = s & 255;
    const float4* x4 = (const float4*)x;
    const float4* sw4 = (const float4*)sw;
    float4 acc[4];
    #pragma unroll
    for (int p = 0; p < 4; p++) acc[p] = make_float4(0.f,0.f,0.f,0.f);
    size_t bb = (size_t)(b << 16);
    #pragma unroll
    for (int ky = 0; ky < 3; ky++) {
        int yy = y + ky - 1; if (yy < 0 || yy >= HH) continue;
        #pragma unroll
        for (int c = -1; c <= 4; c++) {
            int xc = x0 + c; if (xc < 0 || xc >= WWD) continue;
            float4 v = x4[(bb + (yy<<8) + xc)*16 + g];
            #pragma unroll
            for (int p = 0; p < 4; p++) {
                int kx = c - p + 1; if (kx < 0 || kx > 2) continue;
                float4 wv = sw4[(ky*3+kx)*16 + g];
                acc[p].x = fmaf(wv.x, v.x, acc[p].x); acc[p].y = fmaf(wv.y, v.y, acc[p].y);
                acc[p].z = fmaf(wv.z, v.z, acc[p].z); acc[p].w = fmaf(wv.w, v.w, acc[p].w);
            }
        }
    }
    float4* t14 = (float4*)g_t1;
    #pragma unroll
    for (int p = 0; p < 4; p++) {
        float4 r;
        r.x = geluf(acc[p].x); r.y = geluf(acc[p].y);
        r.z = geluf(acc[p].z); r.w = geluf(acc[p].w);
        t14[(size_t)(pbase+p)*16 + g] = r;
    }
}

__global__ __launch_bounds__(256) void k_pe2_s(const float* __restrict__ w)
{
    __shared__ float sw[9*CC];
    for (int t = threadIdx.x; t < 9*CC; t += 256) { int c = t/9, k = t%9; sw[k*CC+c] = w[t]; }
    __syncthreads();
    int g = threadIdx.x & 15, strip = threadIdx.x >> 4;
    int pbase = blockIdx.x*64 + strip*4;
    int b = pbase >> 16, s = pbase & 65535, y = s >> 8, x0 = s & 255;
    const float4* t14 = (const float4*)g_t1;
    const float4* sw4 = (const float4*)sw;
    float4 acc[4];
    #pragma unroll
    for (int p = 0; p < 4; p++) acc[p] = make_float4(0.f,0.f,0.f,0.f);
    size_t bb = (size_t)(b << 16);
    #pragma unroll
    for (int ky = 0; ky < 3; ky++) {
        int yy = y + ky - 1; if (yy < 0 || yy >= HH) continue;
        #pragma unroll
        for (int c = -1; c <= 4; c++) {
            int xc = x0 + c; if (xc < 0 || xc >= WWD) continue;
            float4 v = t14[(bb + (yy<<8) + xc)*16 + g];
            #pragma unroll
            for (int p = 0; p < 4; p++) {
                int kx = c - p + 1; if (kx < 0 || kx > 2) continue;
                float4 wv = sw4[(ky*3+kx)*16 + g];
                acc[p].x = fmaf(wv.x, v.x, acc[p].x); acc[p].y = fmaf(wv.y, v.y, acc[p].y);
                acc[p].z = fmaf(wv.z, v.z, acc[p].z); acc[p].w = fmaf(wv.w, v.w, acc[p].w);
            }
        }
    }
    float4* t24 = (float4*)g_t2;
    #pragma unroll
    for (int p = 0; p < 4; p++) t24[(size_t)(pbase+p)*16 + g] = acc[p];
}

__global__ __launch_bounds__(256) void k_ma_s(const float* __restrict__ dw,
                                              const float* __restrict__ dwb)
{
    __shared__ float sdw[25*CC];
    __shared__ float sdb[CC];
    for (int t = threadIdx.x; t < 25*CC; t += 256) { int c = t/25, k = t%25; sdw[k*CC+c] = dw[t]; }
    for (int t = threadIdx.x; t < CC; t += 256) sdb[t] = dwb[t];
    __syncthreads();
    int g = threadIdx.x & 15, strip = threadIdx.x >> 4;
    int pbase = blockIdx.x*64 + strip*4;
    int b = pbase >> 16, s = pbase & 65535, y = s >> 8, x0 = s & 255;
    const float4* m24 = (const float4*)g_m2;
    const float4* sdw4 = (const float4*)sdw;
    float4 bias4 = ((const float4*)sdb)[g];
    float4 acc[4];
    #pragma unroll
    for (int p = 0; p < 4; p++) acc[p] = bias4;
    size_t bb = (size_t)(b << 16);
    #pragma unroll
    for (int ky = 0; ky < 5; ky++) {
        int yy = y + ky - 2; if (yy < 0 || yy >= HH) continue;
        #pragma unroll
        for (int c = -2; c <= 5; c++) {
            int xc = x0 + c; if (xc < 0 || xc >= WWD) continue;
            float4 v = m24[(bb + (yy<<8) + xc)*16 + g];
            #pragma unroll
            for (int p = 0; p < 4; p++) {
                int kx = c - p + 2; if (kx < 0 || kx > 4) continue;
                float4 wv = sdw4[(ky*5+kx)*16 + g];
                acc[p].x = fmaf(wv.x, v.x, acc[p].x); acc[p].y = fmaf(wv.y, v.y, acc[p].y);
                acc[p].z = fmaf(wv.z, v.z, acc[p].z); acc[p].w = fmaf(wv.w, v.w, acc[p].w);
            }
        }
    }
    const float4* m14 = (const float4*)g_m1;
    const float4* v4  = (const float4*)g_v;
    float4* vm4 = (float4*)g_vm;
    #pragma unroll
    for (int p = 0; p < 4; p++) {
        size_t idx = (size_t)(pbase+p)*16 + g;
        float4 m1v = m14[idx], vv = v4[idx];
        float4 r;
        r.x = vv.x * (m1v.x * (1.f + sigmf(acc[p].x)));
        r.y = vv.y * (m1v.y * (1.f + sigmf(acc[p].y)));
        r.z = vv.z * (m1v.z * (1.f + sigmf(acc[p].z)));
        r.w = vv.w * (m1v.w * (1.f + sigmf(acc[p].w)));
        vm4[idx] = r;
    }
}

// ---------------- launcher: fork/join across 4 streams ----------------
extern "C" void kernel_launch(void* const* d_in, const int* in_sizes, int n_in,
                              void* d_out, int out_size)
{
    const float* x_in   = (const float*)d_in[0];
    const float* mask   = (const float*)d_in[1];
    const float* Wq     = (const float*)d_in[2];
    const float* Wk     = (const float*)d_in[3];
    const float* Wv     = (const float*)d_in[4];
    const float* rescale= (const float*)d_in[5];
    const float* Wp     = (const float*)d_in[6];
    const float* bp     = (const float*)d_in[7];
    const float* mm_w1  = (const float*)d_in[8];
    const float* mm_b1  = (const float*)d_in[9];
    const float* mm_w2  = (const float*)d_in[10];
    const float* mm_b2  = (const float*)d_in[11];
    const float* mm_dw  = (const float*)d_in[12];
    const float* mm_dwb = (const float*)d_in[13];
    const float* pe_w1  = (const float*)d_in[14];
    const float* pe_w2  = (const float*)d_in[15];
    float* out = (float*)d_out;

    float *pm1, *pm2, *pv, *pvm, *pt2, *pwf, *pw2f, *pb2f;
    cudaGetSymbolAddress((void**)&pm1,  g_m1);
    cudaGetSymbolAddress((void**)&pm2,  g_m2);
    cudaGetSymbolAddress((void**)&pv,   g_v);
    cudaGetSymbolAddress((void**)&pvm,  g_vm);
    cudaGetSymbolAddress((void**)&pt2,  g_t2);
    cudaGetSymbolAddress((void**)&pwf,  g_wfold);
    cudaGetSymbolAddress((void**)&pw2f, g_w2f);
    cudaGetSymbolAddress((void**)&pb2f, g_b2f);

    const int SM4_BYTES = (4160*3 + 1024 + 64 + 64 + 256) * 4;   // 55.5 KB

    static cudaStream_t s1 = nullptr, s2 = nullptr, s3 = nullptr;
    static cudaEvent_t evRoot = nullptr, evV = nullptr, evM = nullptr, evP = nullptr, evF = nullptr;
    static int init_done = 0;
    if (!init_done) {
        cudaFuncSetAttribute(k_small4, cudaFuncAttributeMaxDynamicSharedMemorySize, SM4_BYTES);
        cudaStreamCreateWithFlags(&s1, cudaStreamNonBlocking);
        cudaStreamCreateWithFlags(&s2, cudaStreamNonBlocking);
        cudaStreamCreateWithFlags(&s3, cudaStreamNonBlocking);
        cudaEventCreateWithFlags(&evRoot, cudaEventDisableTiming);
        cudaEventCreateWithFlags(&evV,    cudaEventDisableTiming);
        cudaEventCreateWithFlags(&evM,    cudaEventDisableTiming);
        cudaEventCreateWithFlags(&evP,    cudaEventDisableTiming);
        cudaEventCreateWithFlags(&evF,    cudaEventDisableTiming);
        init_done = 1;
    }

    bool multi = (s1 && s2 && s3 && evRoot && evV && evM && evP && evF);

    if (multi) {
        cudaEventRecord(evRoot, 0);
        cudaStreamWaitEvent(s1, evRoot, 0);
        cudaStreamWaitEvent(s2, evRoot, 0);
        cudaStreamWaitEvent(s3, evRoot, 0);

        // s3: fold (off critical path)
        k_fold16<<<16, 256, 0, s3>>>(mm_w1, mm_b1, mm_w2, mm_b2);
        cudaEventRecord(evF, s3);

        // stream 0: gram chain
        k_gram_part<<<NCHUNK, 256>>>(x_in);
        k_gram_red1<<<(32*4096)/256, 256>>>();
        k_small4<<<BN, 256, SM4_BYTES>>>(Wq, Wk, Wp, rescale);

        // s1: mask path — m1 first, then m2 (waits fold)
        k_mv_b<<<NPIX/128, 256, 0, s1>>>(mask, mm_w1, mm_b1, nullptr, pm1, 0);
        cudaStreamWaitEvent(s1, evF, 0);
        k_mv_b<<<NPIX/128, 256, 0, s1>>>(mask, pw2f, pb2f, nullptr, pm2, 0);

        // s2: x path
        k_mv_b<<<NPIX/128, 256, 0, s2>>>(x_in, Wv, nullptr, nullptr, pv, 0);
        cudaEventRecord(evV, s2);
        k_pe1_s<<<NPIX/64, 256, 0, s2>>>(x_in, pe_w1);
        k_pe2_s<<<NPIX/64, 256, 0, s2>>>(pe_w2);
        cudaEventRecord(evP, s2);

        // ma on s1 (needs m1, m2 s1-ordered; v via evV)
        cudaStreamWaitEvent(s1, evV, 0);
        k_ma_s<<<NPIX/64, 256, 0, s1>>>(mm_dw, mm_dwb);
        cudaEventRecord(evM, s1);

        // join
        cudaStreamWaitEvent(0, evM, 0);
        cudaStreamWaitEvent(0, evP, 0);
        k_mv_b<<<NPIX/128, 256>>>(pvm, pwf, bp, pt2, out, 1);
    } else {
        k_fold16<<<16, 256>>>(mm_w1, mm_b1, mm_w2, mm_b2);
        k_gram_part<<<NCHUNK, 256>>>(x_in);
        k_gram_red1<<<(32*4096)/256, 256>>>();
        k_small4<<<BN, 256, SM4_BYTES>>>(Wq, Wk, Wp, rescale);
        k_mv_b<<<NPIX/128, 256>>>(mask, mm_w1, mm_b1, nullptr, pm1, 0);
        k_mv_b<<<NPIX/128, 256>>>(mask, pw2f, pb2f, nullptr, pm2, 0);
        k_mv_b<<<NPIX/128, 256>>>(x_in, Wv, nullptr, nullptr, pv, 0);
        k_pe1_s<<<NPIX/64, 256>>>(x_in, pe_w1);
        k_pe2_s<<<NPIX/64, 256>>>(pe_w2);
        k_ma_s <<<NPIX/64, 256>>>(mm_dw, mm_dwb);
        k_mv_b<<<NPIX/128, 256>>>(pvm, pwf, bp, pt2, out, 1);
    }
}

// round 10
// speedup vs baseline: 1.3729x; 1.1113x over previous
#include <cuda_runtime.h>
#include <math.h>

#define BN 2
#define HH 256
#define WWD 256
#define CC 64
#define PIXB (HH*WWD)
#define NPIX (BN*PIXB)
#define NCHUNK 512

// ---------------- device scratch ----------------
__device__ float g_v [NPIX*CC];
__device__ float g_m1[NPIX*CC];
__device__ float g_m2[NPIX*CC];
__device__ float g_t1[NPIX*CC];
__device__ float g_t2[NPIX*CC];
__device__ float g_vm[NPIX*CC];
__device__ float g_gpart[NCHUNK*4096];
__device__ float g_gpart2[32*4096];
__device__ float g_wfold[BN*4096];
__device__ float g_w2f[4096];
__device__ float g_b2f[64];

__device__ __forceinline__ float sigmf(float x) {
    return 1.0f / (1.0f + __expf(-x));
}
__device__ __forceinline__ float geluf(float v) {
    return 0.5f * v * (1.0f + erff(v * 0.70710678118654752f));
}

// ---------------- Gram partials ----------------
__global__ __launch_bounds__(256) void k_gram_part(const float* __restrict__ x)
{
    __shared__ float sx[8][64];
    int chunk = blockIdx.x;
    int base  = chunk * 256;
    int tid = threadIdx.x;
    int ti = tid >> 4, tj = tid & 15;
    float a00=0,a01=0,a02=0,a03=0, a10=0,a11=0,a12=0,a13=0;
    float a20=0,a21=0,a22=0,a23=0, a30=0,a31=0,a32=0,a33=0;

    for (int pp = 0; pp < 256; pp += 8) {
        __syncthreads();
        int idx = tid * 2;
        int pr = idx >> 6, cc = idx & 63;
        float2 v2 = *(const float2*)&x[(size_t)(base + pp + pr)*CC + cc];
        sx[pr][cc] = v2.x; sx[pr][cc+1] = v2.y;
        __syncthreads();
        #pragma unroll
        for (int p = 0; p < 8; p++) {
            float4 xi = *(const float4*)&sx[p][4*ti];
            float4 xj = *(const float4*)&sx[p][4*tj];
            a00 += xi.x*xj.x; a01 += xi.x*xj.y; a02 += xi.x*xj.z; a03 += xi.x*xj.w;
            a10 += xi.y*xj.x; a11 += xi.y*xj.y; a12 += xi.y*xj.z; a13 += xi.y*xj.w;
            a20 += xi.z*xj.x; a21 += xi.z*xj.y; a22 += xi.z*xj.z; a23 += xi.z*xj.w;
            a30 += xi.w*xj.x; a31 += xi.w*xj.y; a32 += xi.w*xj.z; a33 += xi.w*xj.w;
        }
    }
    float* dst = &g_gpart[(size_t)chunk*4096];
    int r = 4*ti, c = 4*tj;
    dst[(r+0)*64+c+0]=a00; dst[(r+0)*64+c+1]=a01; dst[(r+0)*64+c+2]=a02; dst[(r+0)*64+c+3]=a03;
    dst[(r+1)*64+c+0]=a10; dst[(r+1)*64+c+1]=a11; dst[(r+1)*64+c+2]=a12; dst[(r+1)*64+c+3]=a13;
    dst[(r+2)*64+c+0]=a20; dst[(r+2)*64+c+1]=a21; dst[(r+2)*64+c+2]=a22; dst[(r+2)*64+c+3]=a23;
    dst[(r+3)*64+c+0]=a30; dst[(r+3)*64+c+1]=a31; dst[(r+3)*64+c+2]=a32; dst[(r+3)*64+c+3]=a33;
}

__global__ void k_gram_red1()
{
    int e = blockIdx.x*blockDim.x + threadIdx.x;
    if (e >= 32*4096) return;
    int part = e >> 12, i = e & 4095;
    float s = 0.f;
    #pragma unroll
    for (int c = 0; c < 16; c++)
        s += g_gpart[(size_t)(part*16 + c)*4096 + i];
    g_gpart2[e] = s;
}

// ---------------- fold W2*W1 (16 blocks), b2f = W2 b1 + b2 ----------------
__global__ __launch_bounds__(256) void k_fold16(const float* __restrict__ W1,
                                                const float* __restrict__ b1,
                                                const float* __restrict__ W2,
                                                const float* __restrict__ b2)
{
    __shared__ float sW1[4096];
    int tid = threadIdx.x;
    for (int t = tid; t < 4096; t += 256) sW1[t] = W1[t];
    __syncthreads();
    int t = blockIdx.x*256 + tid;
    int o = t >> 6, c = t & 63;
    float s = 0.f;
    #pragma unroll 8
    for (int i = 0; i < 64; i++) s += W2[o*64+i] * sW1[i*64+c];
    g_w2f[t] = s;
    if (blockIdx.x == 0 && tid < 64) {
        float sb = b2[tid];
        #pragma unroll 8
        for (int i = 0; i < 64; i++) sb += W2[tid*64+i] * b1[i];
        g_b2f[tid] = sb;
    }
}

// ---------------- tiny solve, bank-conflict-free (stride-65 panes) ----------------
#define SP 65
__global__ __launch_bounds__(256) void k_small4(const float* __restrict__ Wq,
                                                const float* __restrict__ Wk,
                                                const float* __restrict__ Wp,
                                                const float* __restrict__ rs)
{
    extern __shared__ float dyn[];
    float* sG   = dyn;            // 64*65 = 4160
    float* sGq  = dyn + 4160;
    float* sW   = dyn + 8320;
    float* sLog = dyn + 12480;
    float* sNq  = dyn + 13504;
    float* sNk  = dyn + 13568;
    float* sPart= dyn + 13632;
    int b = blockIdx.x;
    int tid = threadIdx.x;

    for (int t = tid; t < 4096; t += 256) {
        float s = 0.f;
        #pragma unroll
        for (int c = 0; c < 16; c++)
            s += g_gpart2[(size_t)(b*16 + c)*4096 + t];
        sG[(t >> 6)*SP + (t & 63)] = s;
        sW[(t >> 6)*SP + (t & 63)] = Wq[t];
    }
    __syncthreads();
    for (int t = tid; t < 4096; t += 256) {
        int c = t >> 6, o = t & 63;
        float s0 = 0.f, s1 = 0.f, s2 = 0.f, s3 = 0.f;
        #pragma unroll
        for (int i = 0; i < 64; i += 4) {
            s0 = fmaf(sG[c*SP+i+0], sW[o*SP+i+0], s0);
            s1 = fmaf(sG[c*SP+i+1], sW[o*SP+i+1], s1);
            s2 = fmaf(sG[c*SP+i+2], sW[o*SP+i+2], s2);
            s3 = fmaf(sG[c*SP+i+3], sW[o*SP+i+3], s3);
        }
        sGq[c*SP+o] = (s0+s1) + (s2+s3);
    }
    __syncthreads();
    if (tid < 64) {
        int o = tid;
        float qq = 0.f;
        #pragma unroll 8
        for (int c = 0; c < 64; c++) qq += sW[o*SP+c] * sGq[c*SP+o];
        sNq[o] = fmaxf(sqrtf(fmaxf(qq, 0.f)), 1e-12f);
    }
    __syncthreads();
    for (int t = tid; t < 4096; t += 256) sW[(t >> 6)*SP + (t & 63)] = Wk[t];
    __syncthreads();
    {
        int o = tid >> 2, part = tid & 3;
        float kp = 0.f;
        for (int c = part*16; c < part*16 + 16; c++) {
            float g0 = 0.f, g1 = 0.f, g2 = 0.f, g3 = 0.f;
            #pragma unroll
            for (int i = 0; i < 64; i += 4) {
                g0 = fmaf(sG[c*SP+i+0], sW[o*SP+i+0], g0);
                g1 = fmaf(sG[c*SP+i+1], sW[o*SP+i+1], g1);
                g2 = fmaf(sG[c*SP+i+2], sW[o*SP+i+2], g2);
                g3 = fmaf(sG[c*SP+i+3], sW[o*SP+i+3], g3);
            }
            kp = fmaf(sW[o*SP+c], (g0+g1)+(g2+g3), kp);
        }
        sPart[tid] = kp;
    }
    __syncthreads();
    if (tid < 64) {
        float kk = sPart[4*tid] + sPart[4*tid+1] + sPart[4*tid+2] + sPart[4*tid+3];
        sNk[tid] = fmaxf(sqrtf(fmaxf(kk, 0.f)), 1e-12f);
    }
    __syncthreads();
    for (int t = tid; t < 1024; t += 256) {
        int h = t >> 8, d = (t >> 4) & 15, e = t & 15;
        int rk = h*16 + d, rq = h*16 + e;
        float s0 = 0.f, s1 = 0.f, s2 = 0.f, s3 = 0.f;
        #pragma unroll
        for (int c = 0; c < 64; c += 4) {
            s0 = fmaf(sW[rk*SP+c+0], sGq[(c+0)*SP+rq], s0);
            s1 = fmaf(sW[rk*SP+c+1], sGq[(c+1)*SP+rq], s1);
            s2 = fmaf(sW[rk*SP+c+2], sGq[(c+2)*SP+rq], s2);
            s3 = fmaf(sW[rk*SP+c+3], sGq[(c+3)*SP+rq], s3);
        }
        sLog[t] = ((s0+s1)+(s2+s3)) / (sNk[rk] * sNq[rq]) * rs[h];
    }
    __syncthreads();
    if (tid < 64) {
        float* row = &sLog[tid*16];
        float m = row[0];
        for (int e = 1; e < 16; e++) m = fmaxf(m, row[e]);
        float sum = 0.f;
        for (int e = 0; e < 16; e++) { float ev = expf(row[e]-m); row[e] = ev; sum += ev; }
        float inv = 1.f / sum;
        for (int e = 0; e < 16; e++) row[e] *= inv;
    }
    __syncthreads();
    for (int t = tid; t < 4096; t += 256) sW[(t >> 6)*SP + (t & 63)] = Wp[t];
    __syncthreads();
    for (int t = tid; t < 4096; t += 256) {
        int o = t >> 6, j = t & 63, hj = j >> 4, ej = j & 15;
        float s = 0.f;
        #pragma unroll
        for (int d = 0; d < 16; d++)
            s += sW[o*SP + hj*16 + d] * sLog[(hj*16 + d)*16 + ej];
        g_wfold[b*4096 + t] = s;
    }
}

// ---------------- matvec, one W-row per lane ----------------
__global__ __launch_bounds__(256) void k_mv_b(const float* __restrict__ in,
                                              const float* __restrict__ Wg,
                                              const float* __restrict__ bias,
                                              const float* __restrict__ add,
                                              float* __restrict__ out,
                                              int wsel)
{
    __shared__ float4 sx4[2048];
    float* sx = (float*)sx4;
    int tid = threadIdx.x, lane = tid & 31, wid = tid >> 5;
    int row = (wid >> 2)*32 + lane;
    const float* W = Wg + (wsel ? (int)(blockIdx.x >> 9) * 4096 : 0);

    for (int t = tid; t < 4096; t += 256) sx[(t >> 6)*68 + (t & 63)] = W[t];
    __syncthreads();
    float w[64];
    #pragma unroll
    for (int k = 0; k < 16; k++) {
        float4 a = *(const float4*)&sx[row*68 + 4*k];
        w[4*k+0]=a.x; w[4*k+1]=a.y; w[4*k+2]=a.z; w[4*k+3]=a.w;
    }
    float bb = bias ? bias[row] : 0.f;
    __syncthreads();

    size_t pbase = (size_t)blockIdx.x * 128;
    const float4* in4 = (const float4*)in + pbase*16;
    #pragma unroll
    for (int j = 0; j < 8; j++) sx4[tid + 256*j] = in4[tid + 256*j];
    __syncthreads();

    int pw = (wid & 3) * 32;
    #pragma unroll 2
    for (int q = 0; q < 8; q++) {
        int p0 = pw + q*4;
        float a0 = bb, a1 = bb, a2 = bb, a3 = bb;
        #pragma unroll
        for (int k4 = 0; k4 < 16; k4++) {
            float4 x0 = *(const float4*)&sx[(p0+0)*64 + 4*k4];
            float4 x1 = *(const float4*)&sx[(p0+1)*64 + 4*k4];
            float4 x2 = *(const float4*)&sx[(p0+2)*64 + 4*k4];
            float4 x3 = *(const float4*)&sx[(p0+3)*64 + 4*k4];
            a0 = fmaf(w[4*k4+0], x0.x, a0); a0 = fmaf(w[4*k4+1], x0.y, a0);
            a0 = fmaf(w[4*k4+2], x0.z, a0); a0 = fmaf(w[4*k4+3], x0.w, a0);
            a1 = fmaf(w[4*k4+0], x1.x, a1); a1 = fmaf(w[4*k4+1], x1.y, a1);
            a1 = fmaf(w[4*k4+2], x1.z, a1); a1 = fmaf(w[4*k4+3], x1.w, a1);
            a2 = fmaf(w[4*k4+0], x2.x, a2); a2 = fmaf(w[4*k4+1], x2.y, a2);
            a2 = fmaf(w[4*k4+2], x2.z, a2); a2 = fmaf(w[4*k4+3], x2.w, a2);
            a3 = fmaf(w[4*k4+0], x3.x, a3); a3 = fmaf(w[4*k4+1], x3.y, a3);
            a3 = fmaf(w[4*k4+2], x3.z, a3); a3 = fmaf(w[4*k4+3], x3.w, a3);
        }
        size_t o0 = (pbase + p0)*64 + row;
        if (add) {
            a0 += add[o0]; a1 += add[o0+64]; a2 += add[o0+128]; a3 += add[o0+192];
        }
        out[o0]     = a0;
        out[o0+64]  = a1;
        out[o0+128] = a2;
        out[o0+192] = a3;
    }
}

// ---------------- dwconv, 4-pixel strips ----------------
__global__ __launch_bounds__(256) void k_pe1_s(const float* __restrict__ x,
                                               const float* __restrict__ w)
{
    __shared__ float sw[9*CC];
    for (int t = threadIdx.x; t < 9*CC; t += 256) { int c = t/9, k = t%9; sw[k*CC+c] = w[t]; }
    __syncthreads();
    int g = threadIdx.x & 15, strip = threadIdx.x >> 4;
    int pbase = blockIdx.x*64 + strip*4;
    int b = pbase >> 16, s = pbase & 65535, y = s >> 8, x0 = s & 255;
    const float4* x4 = (const float4*)x;
    const float4* sw4 = (const float4*)sw;
    float4 acc[4];
    #pragma unroll
    for (int p = 0; p < 4; p++) acc[p] = make_float4(0.f,0.f,0.f,0.f);
    size_t bb = (size_t)(b << 16);
    #pragma unroll
    for (int ky = 0; ky < 3; ky++) {
        int yy = y + ky - 1; if (yy < 0 || yy >= HH) continue;
        #pragma unroll
        for (int c = -1; c <= 4; c++) {
            int xc = x0 + c; if (xc < 0 || xc >= WWD) continue;
            float4 v = x4[(bb + (yy<<8) + xc)*16 + g];
            #pragma unroll
            for (int p = 0; p < 4; p++) {
                int kx = c - p + 1; if (kx < 0 || kx > 2) continue;
                float4 wv = sw4[(ky*3+kx)*16 + g];
                acc[p].x = fmaf(wv.x, v.x, acc[p].x); acc[p].y = fmaf(wv.y, v.y, acc[p].y);
                acc[p].z = fmaf(wv.z, v.z, acc[p].z); acc[p].w = fmaf(wv.w, v.w, acc[p].w);
            }
        }
    }
    float4* t14 = (float4*)g_t1;
    #pragma unroll
    for (int p = 0; p < 4; p++) {
        float4 r;
        r.x = geluf(acc[p].x); r.y = geluf(acc[p].y);
        r.z = geluf(acc[p].z); r.w = geluf(acc[p].w);
        t14[(size_t)(pbase+p)*16 + g] = r;
    }
}

__global__ __launch_bounds__(256) void k_pe2_s(const float* __restrict__ w)
{
    __shared__ float sw[9*CC];
    for (int t = threadIdx.x; t < 9*CC; t += 256) { int c = t/9, k = t%9; sw[k*CC+c] = w[t]; }
    __syncthreads();
    int g = threadIdx.x & 15, strip = threadIdx.x >> 4;
    int pbase = blockIdx.x*64 + strip*4;
    int b = pbase >> 16, s = pbase & 65535, y = s >> 8, x0 = s & 255;
    const float4* t14 = (const float4*)g_t1;
    const float4* sw4 = (const float4*)sw;
    float4 acc[4];
    #pragma unroll
    for (int p = 0; p < 4; p++) acc[p] = make_float4(0.f,0.f,0.f,0.f);
    size_t bb = (size_t)(b << 16);
    #pragma unroll
    for (int ky = 0; ky < 3; ky++) {
        int yy = y + ky - 1; if (yy < 0 || yy >= HH) continue;
        #pragma unroll
        for (int c = -1; c <= 4; c++) {
            int xc = x0 + c; if (xc < 0 || xc >= WWD) continue;
            float4 v = t14[(bb + (yy<<8) + xc)*16 + g];
            #pragma unroll
            for (int p = 0; p < 4; p++) {
                int kx = c - p + 1; if (kx < 0 || kx > 2) continue;
                float4 wv = sw4[(ky*3+kx)*16 + g];
                acc[p].x = fmaf(wv.x, v.x, acc[p].x); acc[p].y = fmaf(wv.y, v.y, acc[p].y);
                acc[p].z = fmaf(wv.z, v.z, acc[p].z); acc[p].w = fmaf(wv.w, v.w, acc[p].w);
            }
        }
    }
    float4* t24 = (float4*)g_t2;
    #pragma unroll
    for (int p = 0; p < 4; p++) t24[(size_t)(pbase+p)*16 + g] = acc[p];
}

__global__ __launch_bounds__(256) void k_ma_s(const float* __restrict__ dw,
                                              const float* __restrict__ dwb)
{
    __shared__ float sdw[25*CC];
    __shared__ float sdb[CC];
    for (int t = threadIdx.x; t < 25*CC; t += 256) { int c = t/25, k = t%25; sdw[k*CC+c] = dw[t]; }
    for (int t = threadIdx.x; t < CC; t += 256) sdb[t] = dwb[t];
    __syncthreads();
    int g = threadIdx.x & 15, strip = threadIdx.x >> 4;
    int pbase = blockIdx.x*64 + strip*4;
    int b = pbase >> 16, s = pbase & 65535, y = s >> 8, x0 = s & 255;
    const float4* m24 = (const float4*)g_m2;
    const float4* sdw4 = (const float4*)sdw;
    float4 bias4 = ((const float4*)sdb)[g];
    float4 acc[4];
    #pragma unroll
    for (int p = 0; p < 4; p++) acc[p] = bias4;
    size_t bb = (size_t)(b << 16);
    #pragma unroll
    for (int ky = 0; ky < 5; ky++) {
        int yy = y + ky - 2; if (yy < 0 || yy >= HH) continue;
        #pragma unroll
        for (int c = -2; c <= 5; c++) {
            int xc = x0 + c; if (xc < 0 || xc >= WWD) continue;
            float4 v = m24[(bb + (yy<<8) + xc)*16 + g];
            #pragma unroll
            for (int p = 0; p < 4; p++) {
                int kx = c - p + 2; if (kx < 0 || kx > 4) continue;
                float4 wv = sdw4[(ky*5+kx)*16 + g];
                acc[p].x = fmaf(wv.x, v.x, acc[p].x); acc[p].y = fmaf(wv.y, v.y, acc[p].y);
                acc[p].z = fmaf(wv.z, v.z, acc[p].z); acc[p].w = fmaf(wv.w, v.w, acc[p].w);
            }
        }
    }
    const float4* m14 = (const float4*)g_m1;
    const float4* v4  = (const float4*)g_v;
    float4* vm4 = (float4*)g_vm;
    #pragma unroll
    for (int p = 0; p < 4; p++) {
        size_t idx = (size_t)(pbase+p)*16 + g;
        float4 m1v = m14[idx], vv = v4[idx];
        float4 r;
        r.x = vv.x * (m1v.x * (1.f + sigmf(acc[p].x)));
        r.y = vv.y * (m1v.y * (1.f + sigmf(acc[p].y)));
        r.z = vv.z * (m1v.z * (1.f + sigmf(acc[p].z)));
        r.w = vv.w * (m1v.w * (1.f + sigmf(acc[p].w)));
        vm4[idx] = r;
    }
}

// ---------------- launcher: R7 schedule, fold16 + small4 swapped in ----------------
extern "C" void kernel_launch(void* const* d_in, const int* in_sizes, int n_in,
                              void* d_out, int out_size)
{
    const float* x_in   = (const float*)d_in[0];
    const float* mask   = (const float*)d_in[1];
    const float* Wq     = (const float*)d_in[2];
    const float* Wk     = (const float*)d_in[3];
    const float* Wv     = (const float*)d_in[4];
    const float* rescale= (const float*)d_in[5];
    const float* Wp     = (const float*)d_in[6];
    const float* bp     = (const float*)d_in[7];
    const float* mm_w1  = (const float*)d_in[8];
    const float* mm_b1  = (const float*)d_in[9];
    const float* mm_w2  = (const float*)d_in[10];
    const float* mm_b2  = (const float*)d_in[11];
    const float* mm_dw  = (const float*)d_in[12];
    const float* mm_dwb = (const float*)d_in[13];
    const float* pe_w1  = (const float*)d_in[14];
    const float* pe_w2  = (const float*)d_in[15];
    float* out = (float*)d_out;

    float *pm1, *pm2, *pv, *pvm, *pt2, *pwf, *pw2f, *pb2f;
    cudaGetSymbolAddress((void**)&pm1,  g_m1);
    cudaGetSymbolAddress((void**)&pm2,  g_m2);
    cudaGetSymbolAddress((void**)&pv,   g_v);
    cudaGetSymbolAddress((void**)&pvm,  g_vm);
    cudaGetSymbolAddress((void**)&pt2,  g_t2);
    cudaGetSymbolAddress((void**)&pwf,  g_wfold);
    cudaGetSymbolAddress((void**)&pw2f, g_w2f);
    cudaGetSymbolAddress((void**)&pb2f, g_b2f);

    const int SM4_BYTES = (4160*3 + 1024 + 64 + 64 + 256) * 4;   // 55.5 KB

    static cudaStream_t s1 = nullptr, s2 = nullptr;
    static cudaEvent_t evRoot = nullptr, evV = nullptr, evM = nullptr, evP = nullptr;
    static int init_done = 0;
    if (!init_done) {
        cudaFuncSetAttribute(k_small4, cudaFuncAttributeMaxDynamicSharedMemorySize, SM4_BYTES);
        cudaStreamCreateWithFlags(&s1, cudaStreamNonBlocking);
        cudaStreamCreateWithFlags(&s2, cudaStreamNonBlocking);
        cudaEventCreateWithFlags(&evRoot, cudaEventDisableTiming);
        cudaEventCreateWithFlags(&evV,    cudaEventDisableTiming);
        cudaEventCreateWithFlags(&evM,    cudaEventDisableTiming);
        cudaEventCreateWithFlags(&evP,    cudaEventDisableTiming);
        init_done = 1;
    }

    bool multi = (s1 && s2 && evRoot && evV && evM && evP);

    if (multi) {
        // fork (R7 structure)
        cudaEventRecord(evRoot, 0);
        cudaStreamWaitEvent(s1, evRoot, 0);
        cudaStreamWaitEvent(s2, evRoot, 0);

        // stream 0: gram chain
        k_gram_part<<<NCHUNK, 256>>>(x_in);
        k_gram_red1<<<(32*4096)/256, 256>>>();
        k_small4<<<BN, 256, SM4_BYTES>>>(Wq, Wk, Wp, rescale);

        // s1: mask path (fold16 at head — now ~3 us instead of 21)
        k_fold16<<<16, 256, 0, s1>>>(mm_w1, mm_b1, mm_w2, mm_b2);
        k_mv_b<<<NPIX/128, 256, 0, s1>>>(mask, mm_w1, mm_b1, nullptr, pm1, 0);
        k_mv_b<<<NPIX/128, 256, 0, s1>>>(mask, pw2f, pb2f, nullptr, pm2, 0);

        // s2: x path (v, pe1, pe2)
        k_mv_b<<<NPIX/128, 256, 0, s2>>>(x_in, Wv, nullptr, nullptr, pv, 0);
        cudaEventRecord(evV, s2);
        k_pe1_s<<<NPIX/64, 256, 0, s2>>>(x_in, pe_w1);
        k_pe2_s<<<NPIX/64, 256, 0, s2>>>(pe_w2);
        cudaEventRecord(evP, s2);

        // ma on s1: needs m1, m2 (s1-ordered) and v (evV)
        cudaStreamWaitEvent(s1, evV, 0);
        k_ma_s<<<NPIX/64, 256, 0, s1>>>(mm_dw, mm_dwb);
        cudaEventRecord(evM, s1);

        // join: final needs small4 (stream-0 ordered), ma (evM), pe2 (evP)
        cudaStreamWaitEvent(0, evM, 0);
        cudaStreamWaitEvent(0, evP, 0);
        k_mv_b<<<NPIX/128, 256>>>(pvm, pwf, bp, pt2, out, 1);
    } else {
        k_fold16<<<16, 256>>>(mm_w1, mm_b1, mm_w2, mm_b2);
        k_gram_part<<<NCHUNK, 256>>>(x_in);
        k_gram_red1<<<(32*4096)/256, 256>>>();
        k_small4<<<BN, 256, SM4_BYTES>>>(Wq, Wk, Wp, rescale);
        k_mv_b<<<NPIX/128, 256>>>(mask, mm_w1, mm_b1, nullptr, pm1, 0);
        k_mv_b<<<NPIX/128, 256>>>(mask, pw2f, pb2f, nullptr, pm2, 0);
        k_mv_b<<<NPIX/128, 256>>>(x_in, Wv, nullptr, nullptr, pv, 0);
        k_pe1_s<<<NPIX/64, 256>>>(x_in, pe_w1);
        k_pe2_s<<<NPIX/64, 256>>>(pe_w2);
        k_ma_s <<<NPIX/64, 256>>>(mm_dw, mm_dwb);
        k_mv_b<<<NPIX/128, 256>>>(pvm, pwf, bp, pt2, out, 1);
    }
}

// round 12
// speedup vs baseline: 1.4218x; 1.0357x over previous
#include <cuda_runtime.h>
#include <math.h>

#define BN 2
#define HH 256
#define WWD 256
#define CC 64
#define PIXB (HH*WWD)
#define NPIX (BN*PIXB)
#define NCHUNK 512

// ---------------- device scratch ----------------
__device__ float g_v [NPIX*CC];
__device__ float g_m1[NPIX*CC];
__device__ float g_m2[NPIX*CC];
__device__ float g_t1[NPIX*CC];
__device__ float g_t2[NPIX*CC];
__device__ float g_vm[NPIX*CC];
__device__ float g_gpart[NCHUNK*4096];
__device__ float g_gpart2[32*4096];
__device__ float g_wfold[BN*4096];
__device__ float g_w2f[4096];
__device__ float g_b2f[64];

__device__ __forceinline__ float sigmf(float x) {
    return 1.0f / (1.0f + __expf(-x));
}
__device__ __forceinline__ float geluf(float v) {
    return 0.5f * v * (1.0f + erff(v * 0.70710678118654752f));
}

// ---------------- Gram partials ----------------
__global__ __launch_bounds__(256) void k_gram_part(const float* __restrict__ x)
{
    __shared__ float sx[8][64];
    int chunk = blockIdx.x;
    int base  = chunk * 256;
    int tid = threadIdx.x;
    int ti = tid >> 4, tj = tid & 15;
    float a00=0,a01=0,a02=0,a03=0, a10=0,a11=0,a12=0,a13=0;
    float a20=0,a21=0,a22=0,a23=0, a30=0,a31=0,a32=0,a33=0;

    for (int pp = 0; pp < 256; pp += 8) {
        __syncthreads();
        int idx = tid * 2;
        int pr = idx >> 6, cc = idx & 63;
        float2 v2 = *(const float2*)&x[(size_t)(base + pp + pr)*CC + cc];
        sx[pr][cc] = v2.x; sx[pr][cc+1] = v2.y;
        __syncthreads();
        #pragma unroll
        for (int p = 0; p < 8; p++) {
            float4 xi = *(const float4*)&sx[p][4*ti];
            float4 xj = *(const float4*)&sx[p][4*tj];
            a00 += xi.x*xj.x; a01 += xi.x*xj.y; a02 += xi.x*xj.z; a03 += xi.x*xj.w;
            a10 += xi.y*xj.x; a11 += xi.y*xj.y; a12 += xi.y*xj.z; a13 += xi.y*xj.w;
            a20 += xi.z*xj.x; a21 += xi.z*xj.y; a22 += xi.z*xj.z; a23 += xi.z*xj.w;
            a30 += xi.w*xj.x; a31 += xi.w*xj.y; a32 += xi.w*xj.z; a33 += xi.w*xj.w;
        }
    }
    float* dst = &g_gpart[(size_t)chunk*4096];
    int r = 4*ti, c = 4*tj;
    dst[(r+0)*64+c+0]=a00; dst[(r+0)*64+c+1]=a01; dst[(r+0)*64+c+2]=a02; dst[(r+0)*64+c+3]=a03;
    dst[(r+1)*64+c+0]=a10; dst[(r+1)*64+c+1]=a11; dst[(r+1)*64+c+2]=a12; dst[(r+1)*64+c+3]=a13;
    dst[(r+2)*64+c+0]=a20; dst[(r+2)*64+c+1]=a21; dst[(r+2)*64+c+2]=a22; dst[(r+2)*64+c+3]=a23;
    dst[(r+3)*64+c+0]=a30; dst[(r+3)*64+c+1]=a31; dst[(r+3)*64+c+2]=a32; dst[(r+3)*64+c+3]=a33;
}

__global__ void k_gram_red1()
{
    int e = blockIdx.x*blockDim.x + threadIdx.x;
    if (e >= 32*4096) return;
    int part = e >> 12, i = e & 4095;
    float s = 0.f;
    #pragma unroll
    for (int c = 0; c < 16; c++)
        s += g_gpart[(size_t)(part*16 + c)*4096 + i];
    g_gpart2[e] = s;
}

// ---------------- fold W2*W1 (16 blocks, both operands staged) ----------------
__global__ __launch_bounds__(256) void k_fold16(const float* __restrict__ W1,
                                                const float* __restrict__ b1,
                                                const float* __restrict__ W2,
                                                const float* __restrict__ b2)
{
    __shared__ float sW1[4096];
    __shared__ float sW2r[4*64];
    int tid = threadIdx.x;
    for (int t = tid; t < 4096; t += 256) sW1[t] = W1[t];
    int obase = blockIdx.x * 4;
    for (int t = tid; t < 4*64; t += 256) sW2r[t] = W2[obase*64 + t];
    __syncthreads();
    int t = blockIdx.x*256 + tid;
    int o = t >> 6, c = t & 63;
    float s = 0.f;
    #pragma unroll 8
    for (int i = 0; i < 64; i++) s += sW2r[(o - obase)*64 + i] * sW1[i*64+c];
    g_w2f[t] = s;
    if (blockIdx.x == 0 && tid < 64) {
        float sb = b2[tid];
        #pragma unroll 8
        for (int i = 0; i < 64; i++) sb += W2[tid*64+i] * b1[i];
        g_b2f[tid] = sb;
    }
}

// ---------------- tiny solve, bank-conflict-free (stride-65 panes) ----------------
#define SP 65
__global__ __launch_bounds__(256) void k_small4(const float* __restrict__ Wq,
                                                const float* __restrict__ Wk,
                                                const float* __restrict__ Wp,
                                                const float* __restrict__ rs)
{
    extern __shared__ float dyn[];
    float* sG   = dyn;
    float* sGq  = dyn + 4160;
    float* sW   = dyn + 8320;
    float* sLog = dyn + 12480;
    float* sNq  = dyn + 13504;
    float* sNk  = dyn + 13568;
    float* sPart= dyn + 13632;
    int b = blockIdx.x;
    int tid = threadIdx.x;

    for (int t = tid; t < 4096; t += 256) {
        float s = 0.f;
        #pragma unroll
        for (int c = 0; c < 16; c++)
            s += g_gpart2[(size_t)(b*16 + c)*4096 + t];
        sG[(t >> 6)*SP + (t & 63)] = s;
        sW[(t >> 6)*SP + (t & 63)] = Wq[t];
    }
    __syncthreads();
    for (int t = tid; t < 4096; t += 256) {
        int c = t >> 6, o = t & 63;
        float s0 = 0.f, s1 = 0.f, s2 = 0.f, s3 = 0.f;
        #pragma unroll
        for (int i = 0; i < 64; i += 4) {
            s0 = fmaf(sG[c*SP+i+0], sW[o*SP+i+0], s0);
            s1 = fmaf(sG[c*SP+i+1], sW[o*SP+i+1], s1);
            s2 = fmaf(sG[c*SP+i+2], sW[o*SP+i+2], s2);
            s3 = fmaf(sG[c*SP+i+3], sW[o*SP+i+3], s3);
        }
        sGq[c*SP+o] = (s0+s1) + (s2+s3);
    }
    __syncthreads();
    if (tid < 64) {
        int o = tid;
        float qq = 0.f;
        #pragma unroll 8
        for (int c = 0; c < 64; c++) qq += sW[o*SP+c] * sGq[c*SP+o];
        sNq[o] = fmaxf(sqrtf(fmaxf(qq, 0.f)), 1e-12f);
    }
    __syncthreads();
    for (int t = tid; t < 4096; t += 256) sW[(t >> 6)*SP + (t & 63)] = Wk[t];
    __syncthreads();
    {
        int o = tid >> 2, part = tid & 3;
        float kp = 0.f;
        for (int c = part*16; c < part*16 + 16; c++) {
            float g0 = 0.f, g1 = 0.f, g2 = 0.f, g3 = 0.f;
            #pragma unroll
            for (int i = 0; i < 64; i += 4) {
                g0 = fmaf(sG[c*SP+i+0], sW[o*SP+i+0], g0);
                g1 = fmaf(sG[c*SP+i+1], sW[o*SP+i+1], g1);
                g2 = fmaf(sG[c*SP+i+2], sW[o*SP+i+2], g2);
                g3 = fmaf(sG[c*SP+i+3], sW[o*SP+i+3], g3);
            }
            kp = fmaf(sW[o*SP+c], (g0+g1)+(g2+g3), kp);
        }
        sPart[tid] = kp;
    }
    __syncthreads();
    if (tid < 64) {
        float kk = sPart[4*tid] + sPart[4*tid+1] + sPart[4*tid+2] + sPart[4*tid+3];
        sNk[tid] = fmaxf(sqrtf(fmaxf(kk, 0.f)), 1e-12f);
    }
    __syncthreads();
    for (int t = tid; t < 1024; t += 256) {
        int h = t >> 8, d = (t >> 4) & 15, e = t & 15;
        int rk = h*16 + d, rq = h*16 + e;
        float s0 = 0.f, s1 = 0.f, s2 = 0.f, s3 = 0.f;
        #pragma unroll
        for (int c = 0; c < 64; c += 4) {
            s0 = fmaf(sW[rk*SP+c+0], sGq[(c+0)*SP+rq], s0);
            s1 = fmaf(sW[rk*SP+c+1], sGq[(c+1)*SP+rq], s1);
            s2 = fmaf(sW[rk*SP+c+2], sGq[(c+2)*SP+rq], s2);
            s3 = fmaf(sW[rk*SP+c+3], sGq[(c+3)*SP+rq], s3);
        }
        sLog[t] = ((s0+s1)+(s2+s3)) / (sNk[rk] * sNq[rq]) * rs[h];
    }
    __syncthreads();
    if (tid < 64) {
        float* row = &sLog[tid*16];
        float m = row[0];
        for (int e = 1; e < 16; e++) m = fmaxf(m, row[e]);
        float sum = 0.f;
        for (int e = 0; e < 16; e++) { float ev = expf(row[e]-m); row[e] = ev; sum += ev; }
        float inv = 1.f / sum;
        for (int e = 0; e < 16; e++) row[e] *= inv;
    }
    __syncthreads();
    for (int t = tid; t < 4096; t += 256) sW[(t >> 6)*SP + (t & 63)] = Wp[t];
    __syncthreads();
    for (int t = tid; t < 4096; t += 256) {
        int o = t >> 6, j = t & 63, hj = j >> 4, ej = j & 15;
        float s = 0.f;
        #pragma unroll
        for (int d = 0; d < 16; d++)
            s += sW[o*SP + hj*16 + d] * sLog[(hj*16 + d)*16 + ej];
        g_wfold[b*4096 + t] = s;
    }
}

// ---------------- matvec, one W-row per lane ----------------
__global__ __launch_bounds__(256) void k_mv_b(const float* __restrict__ in,
                                              const float* __restrict__ Wg,
                                              const float* __restrict__ bias,
                                              const float* __restrict__ add,
                                              float* __restrict__ out,
                                              int wsel)
{
    __shared__ float4 sx4[2048];
    float* sx = (float*)sx4;
    int tid = threadIdx.x, lane = tid & 31, wid = tid >> 5;
    int row = (wid >> 2)*32 + lane;
    const float* W = Wg + (wsel ? (int)(blockIdx.x >> 9) * 4096 : 0);

    for (int t = tid; t < 4096; t += 256) sx[(t >> 6)*68 + (t & 63)] = W[t];
    __syncthreads();
    float w[64];
    #pragma unroll
    for (int k = 0; k < 16; k++) {
        float4 a = *(const float4*)&sx[row*68 + 4*k];
        w[4*k+0]=a.x; w[4*k+1]=a.y; w[4*k+2]=a.z; w[4*k+3]=a.w;
    }
    float bb = bias ? bias[row] : 0.f;
    __syncthreads();

    size_t pbase = (size_t)blockIdx.x * 128;
    const float4* in4 = (const float4*)in + pbase*16;
    #pragma unroll
    for (int j = 0; j < 8; j++) sx4[tid + 256*j] = in4[tid + 256*j];
    __syncthreads();

    int pw = (wid & 3) * 32;
    #pragma unroll 2
    for (int q = 0; q < 8; q++) {
        int p0 = pw + q*4;
        float a0 = bb, a1 = bb, a2 = bb, a3 = bb;
        #pragma unroll
        for (int k4 = 0; k4 < 16; k4++) {
            float4 x0 = *(const float4*)&sx[(p0+0)*64 + 4*k4];
            float4 x1 = *(const float4*)&sx[(p0+1)*64 + 4*k4];
            float4 x2 = *(const float4*)&sx[(p0+2)*64 + 4*k4];
            float4 x3 = *(const float4*)&sx[(p0+3)*64 + 4*k4];
            a0 = fmaf(w[4*k4+0], x0.x, a0); a0 = fmaf(w[4*k4+1], x0.y, a0);
            a0 = fmaf(w[4*k4+2], x0.z, a0); a0 = fmaf(w[4*k4+3], x0.w, a0);
            a1 = fmaf(w[4*k4+0], x1.x, a1); a1 = fmaf(w[4*k4+1], x1.y, a1);
            a1 = fmaf(w[4*k4+2], x1.z, a1); a1 = fmaf(w[4*k4+3], x1.w, a1);
            a2 = fmaf(w[4*k4+0], x2.x, a2); a2 = fmaf(w[4*k4+1], x2.y, a2);
            a2 = fmaf(w[4*k4+2], x2.z, a2); a2 = fmaf(w[4*k4+3], x2.w, a2);
            a3 = fmaf(w[4*k4+0], x3.x, a3); a3 = fmaf(w[4*k4+1], x3.y, a3);
            a3 = fmaf(w[4*k4+2], x3.z, a3); a3 = fmaf(w[4*k4+3], x3.w, a3);
        }
        size_t o0 = (pbase + p0)*64 + row;
        if (add) {
            a0 += add[o0]; a1 += add[o0+64]; a2 += add[o0+128]; a3 += add[o0+192];
        }
        out[o0]     = a0;
        out[o0+64]  = a1;
        out[o0+128] = a2;
        out[o0+192] = a3;
    }
}

// ---------------- dual matvec: m1 = W1*mask + b1 ; m2 = W2f*mask + b2f ----------------
// 512 thr = 16 warps: mat = wid>>3, row = ((wid>>2)&1)*32 + lane, pixel set = (wid&3)*32.
__global__ __launch_bounds__(512) void k_mv_dual(const float* __restrict__ mask,
                                                 const float* __restrict__ W1,
                                                 const float* __restrict__ b1)
{
    __shared__ float4 sx4[2048];
    float* sx = (float*)sx4;
    int tid = threadIdx.x, lane = tid & 31, wid = tid >> 5;
    int mat = wid >> 3;
    int row = ((wid >> 2) & 1)*32 + lane;

    // stage W1, mat-0 warps grab rows
    for (int t = tid; t < 4096; t += 512) sx[(t >> 6)*68 + (t & 63)] = W1[t];
    __syncthreads();
    float w[64];
    if (mat == 0) {
        #pragma unroll
        for (int k = 0; k < 16; k++) {
            float4 a = *(const float4*)&sx[row*68 + 4*k];
            w[4*k+0]=a.x; w[4*k+1]=a.y; w[4*k+2]=a.z; w[4*k+3]=a.w;
        }
    }
    __syncthreads();
    // stage W2f, mat-1 warps grab rows
    for (int t = tid; t < 4096; t += 512) sx[(t >> 6)*68 + (t & 63)] = g_w2f[t];
    __syncthreads();
    if (mat == 1) {
        #pragma unroll
        for (int k = 0; k < 16; k++) {
            float4 a = *(const float4*)&sx[row*68 + 4*k];
            w[4*k+0]=a.x; w[4*k+1]=a.y; w[4*k+2]=a.z; w[4*k+3]=a.w;
        }
    }
    float bb = (mat == 0) ? b1[row] : g_b2f[row];
    __syncthreads();

    // mask tile (128 px), coalesced
    size_t pbase = (size_t)blockIdx.x * 128;
    const float4* in4 = (const float4*)mask + pbase*16;
    #pragma unroll
    for (int j = 0; j < 4; j++) sx4[tid + 512*j] = in4[tid + 512*j];
    __syncthreads();

    float* dst = (mat == 0) ? g_m1 : g_m2;
    int pw = (wid & 3) * 32;
    #pragma unroll 2
    for (int q = 0; q < 8; q++) {
        int p0 = pw + q*4;
        float a0 = bb, a1 = bb, a2 = bb, a3 = bb;
        #pragma unroll
        for (int k4 = 0; k4 < 16; k4++) {
            float4 x0 = *(const float4*)&sx[(p0+0)*64 + 4*k4];
            float4 x1 = *(const float4*)&sx[(p0+1)*64 + 4*k4];
            float4 x2 = *(const float4*)&sx[(p0+2)*64 + 4*k4];
            float4 x3 = *(const float4*)&sx[(p0+3)*64 + 4*k4];
            a0 = fmaf(w[4*k4+0], x0.x, a0); a0 = fmaf(w[4*k4+1], x0.y, a0);
            a0 = fmaf(w[4*k4+2], x0.z, a0); a0 = fmaf(w[4*k4+3], x0.w, a0);
            a1 = fmaf(w[4*k4+0], x1.x, a1); a1 = fmaf(w[4*k4+1], x1.y, a1);
            a1 = fmaf(w[4*k4+2], x1.z, a1); a1 = fmaf(w[4*k4+3], x1.w, a1);
            a2 = fmaf(w[4*k4+0], x2.x, a2); a2 = fmaf(w[4*k4+1], x2.y, a2);
            a2 = fmaf(w[4*k4+2], x2.z, a2); a2 = fmaf(w[4*k4+3], x2.w, a2);
            a3 = fmaf(w[4*k4+0], x3.x, a3); a3 = fmaf(w[4*k4+1], x3.y, a3);
            a3 = fmaf(w[4*k4+2], x3.z, a3); a3 = fmaf(w[4*k4+3], x3.w, a3);
        }
        size_t o0 = (pbase + p0)*64 + row;
        dst[o0]     = a0;
        dst[o0+64]  = a1;
        dst[o0+128] = a2;
        dst[o0+192] = a3;
    }
}

// ---------------- dwconv, 4-pixel strips ----------------
__global__ __launch_bounds__(256) void k_pe1_s(const float* __restrict__ x,
                                               const float* __restrict__ w)
{
    __shared__ float sw[9*CC];
    for (int t = threadIdx.x; t < 9*CC; t += 256) { int c = t/9, k = t%9; sw[k*CC+c] = w[t]; }
    __syncthreads();
    int g = threadIdx.x & 15, strip = threadIdx.x >> 4;
    int pbase = blockIdx.x*64 + strip*4;
    int b = pbase >> 16, s = pbase & 65535, y = s >> 8, x0 = s & 255;
    const float4* x4 = (const float4*)x;
    const float4* sw4 = (const float4*)sw;
    float4 acc[4];
    #pragma unroll
    for (int p = 0; p < 4; p++) acc[p] = make_float4(0.f,0.f,0.f,0.f);
    size_t bb = (size_t)(b << 16);
    #pragma unroll
    for (int ky = 0; ky < 3; ky++) {
        int yy = y + ky - 1; if (yy < 0 || yy >= HH) continue;
        #pragma unroll
        for (int c = -1; c <= 4; c++) {
            int xc = x0 + c; if (xc < 0 || xc >= WWD) continue;
            float4 v = x4[(bb + (yy<<8) + xc)*16 + g];
            #pragma unroll
            for (int p = 0; p < 4; p++) {
                int kx = c - p + 1; if (kx < 0 || kx > 2) continue;
                float4 wv = sw4[(ky*3+kx)*16 + g];
                acc[p].x = fmaf(wv.x, v.x, acc[p].x); acc[p].y = fmaf(wv.y, v.y, acc[p].y);
                acc[p].z = fmaf(wv.z, v.z, acc[p].z); acc[p].w = fmaf(wv.w, v.w, acc[p].w);
            }
        }
    }
    float4* t14 = (float4*)g_t1;
    #pragma unroll
    for (int p = 0; p < 4; p++) {
        float4 r;
        r.x = geluf(acc[p].x); r.y = geluf(acc[p].y);
        r.z = geluf(acc[p].z); r.w = geluf(acc[p].w);
        t14[(size_t)(pbase+p)*16 + g] = r;
    }
}

__global__ __launch_bounds__(256) void k_pe2_s(const float* __restrict__ w)
{
    __shared__ float sw[9*CC];
    for (int t = threadIdx.x; t < 9*CC; t += 256) { int c = t/9, k = t%9; sw[k*CC+c] = w[t]; }
    __syncthreads();
    int g = threadIdx.x & 15, strip = threadIdx.x >> 4;
    int pbase = blockIdx.x*64 + strip*4;
    int b = pbase >> 16, s = pbase & 65535, y = s >> 8, x0 = s & 255;
    const float4* t14 = (const float4*)g_t1;
    const float4* sw4 = (const float4*)sw;
    float4 acc[4];
    #pragma unroll
    for (int p = 0; p < 4; p++) acc[p] = make_float4(0.f,0.f,0.f,0.f);
    size_t bb = (size_t)(b << 16);
    #pragma unroll
    for (int ky = 0; ky < 3; ky++) {
        int yy = y + ky - 1; if (yy < 0 || yy >= HH) continue;
        #pragma unroll
        for (int c = -1; c <= 4; c++) {
            int xc = x0 + c; if (xc < 0 || xc >= WWD) continue;
            float4 v = t14[(bb + (yy<<8) + xc)*16 + g];
            #pragma unroll
            for (int p = 0; p < 4; p++) {
                int kx = c - p + 1; if (kx < 0 || kx > 2) continue;
                float4 wv = sw4[(ky*3+kx)*16 + g];
                acc[p].x = fmaf(wv.x, v.x, acc[p].x); acc[p].y = fmaf(wv.y, v.y, acc[p].y);
                acc[p].z = fmaf(wv.z, v.z, acc[p].z); acc[p].w = fmaf(wv.w, v.w, acc[p].w);
            }
        }
    }
    float4* t24 = (float4*)g_t2;
    #pragma unroll
    for (int p = 0; p < 4; p++) t24[(size_t)(pbase+p)*16 + g] = acc[p];
}

__global__ __launch_bounds__(256) void k_ma_s(const float* __restrict__ dw,
                                              const float* __restrict__ dwb)
{
    __shared__ float sdw[25*CC];
    __shared__ float sdb[CC];
    for (int t = threadIdx.x; t < 25*CC; t += 256) { int c = t/25, k = t%25; sdw[k*CC+c] = dw[t]; }
    for (int t = threadIdx.x; t < CC; t += 256) sdb[t] = dwb[t];
    __syncthreads();
    int g = threadIdx.x & 15, strip = threadIdx.x >> 4;
    int pbase = blockIdx.x*64 + strip*4;
    int b = pbase >> 16, s = pbase & 65535, y = s >> 8, x0 = s & 255;
    const float4* m24 = (const float4*)g_m2;
    const float4* sdw4 = (const float4*)sdw;
    float4 bias4 = ((const float4*)sdb)[g];
    float4 acc[4];
    #pragma unroll
    for (int p = 0; p < 4; p++) acc[p] = bias4;
    size_t bb = (size_t)(b << 16);
    #pragma unroll
    for (int ky = 0; ky < 5; ky++) {
        int yy = y + ky - 2; if (yy < 0 || yy >= HH) continue;
        #pragma unroll
        for (int c = -2; c <= 5; c++) {
            int xc = x0 + c; if (xc < 0 || xc >= WWD) continue;
            float4 v = m24[(bb + (yy<<8) + xc)*16 + g];
            #pragma unroll
            for (int p = 0; p < 4; p++) {
                int kx = c - p + 2; if (kx < 0 || kx > 4) continue;
                float4 wv = sdw4[(ky*5+kx)*16 + g];
                acc[p].x = fmaf(wv.x, v.x, acc[p].x); acc[p].y = fmaf(wv.y, v.y, acc[p].y);
                acc[p].z = fmaf(wv.z, v.z, acc[p].z); acc[p].w = fmaf(wv.w, v.w, acc[p].w);
            }
        }
    }
    const float4* m14 = (const float4*)g_m1;
    const float4* v4  = (const float4*)g_v;
    float4* vm4 = (float4*)g_vm;
    #pragma unroll
    for (int p = 0; p < 4; p++) {
        size_t idx = (size_t)(pbase+p)*16 + g;
        float4 m1v = m14[idx], vv = v4[idx];
        float4 r;
        r.x = vv.x * (m1v.x * (1.f + sigmf(acc[p].x)));
        r.y = vv.y * (m1v.y * (1.f + sigmf(acc[p].y)));
        r.z = vv.z * (m1v.z * (1.f + sigmf(acc[p].z)));
        r.w = vv.w * (m1v.w * (1.f + sigmf(acc[p].w)));
        vm4[idx] = r;
    }
}

// ---------------- launcher: R10 schedule + fold16-staged + mv_dual ----------------
extern "C" void kernel_launch(void* const* d_in, const int* in_sizes, int n_in,
                              void* d_out, int out_size)
{
    const float* x_in   = (const float*)d_in[0];
    const float* mask   = (const float*)d_in[1];
    const float* Wq     = (const float*)d_in[2];
    const float* Wk     = (const float*)d_in[3];
    const float* Wv     = (const float*)d_in[4];
    const float* rescale= (const float*)d_in[5];
    const float* Wp     = (const float*)d_in[6];
    const float* bp     = (const float*)d_in[7];
    const float* mm_w1  = (const float*)d_in[8];
    const float* mm_b1  = (const float*)d_in[9];
    const float* mm_w2  = (const float*)d_in[10];
    const float* mm_b2  = (const float*)d_in[11];
    const float* mm_dw  = (const float*)d_in[12];
    const float* mm_dwb = (const float*)d_in[13];
    const float* pe_w1  = (const float*)d_in[14];
    const float* pe_w2  = (const float*)d_in[15];
    float* out = (float*)d_out;

    float *pv, *pvm, *pt2, *pwf;
    cudaGetSymbolAddress((void**)&pv,   g_v);
    cudaGetSymbolAddress((void**)&pvm,  g_vm);
    cudaGetSymbolAddress((void**)&pt2,  g_t2);
    cudaGetSymbolAddress((void**)&pwf,  g_wfold);

    const int SM4_BYTES = (4160*3 + 1024 + 64 + 64 + 256) * 4;

    static cudaStream_t s1 = nullptr, s2 = nullptr;
    static cudaEvent_t evRoot = nullptr, evV = nullptr, evM = nullptr, evP = nullptr;
    static int init_done = 0;
    if (!init_done) {
        cudaFuncSetAttribute(k_small4, cudaFuncAttributeMaxDynamicSharedMemorySize, SM4_BYTES);
        cudaStreamCreateWithFlags(&s1, cudaStreamNonBlocking);
        cudaStreamCreateWithFlags(&s2, cudaStreamNonBlocking);
        cudaEventCreateWithFlags(&evRoot, cudaEventDisableTiming);
        cudaEventCreateWithFlags(&evV,    cudaEventDisableTiming);
        cudaEventCreateWithFlags(&evM,    cudaEventDisableTiming);
        cudaEventCreateWithFlags(&evP,    cudaEventDisableTiming);
        init_done = 1;
    }

    bool multi = (s1 && s2 && evRoot && evV && evM && evP);

    if (multi) {
        cudaEventRecord(evRoot, 0);
        cudaStreamWaitEvent(s1, evRoot, 0);
        cudaStreamWaitEvent(s2, evRoot, 0);

        // stream 0: gram chain
        k_gram_part<<<NCHUNK, 256>>>(x_in);
        k_gram_red1<<<(32*4096)/256, 256>>>();
        k_small4<<<BN, 256, SM4_BYTES>>>(Wq, Wk, Wp, rescale);

        // s1: mask path (fold staged, fused m1+m2)
        k_fold16<<<16, 256, 0, s1>>>(mm_w1, mm_b1, mm_w2, mm_b2);
        k_mv_dual<<<NPIX/128, 512, 0, s1>>>(mask, mm_w1, mm_b1);

        // s2: x path (v, pe1, pe2)
        k_mv_b<<<NPIX/128, 256, 0, s2>>>(x_in, Wv, nullptr, nullptr, pv, 0);
        cudaEventRecord(evV, s2);
        k_pe1_s<<<NPIX/64, 256, 0, s2>>>(x_in, pe_w1);
        k_pe2_s<<<NPIX/64, 256, 0, s2>>>(pe_w2);
        cudaEventRecord(evP, s2);

        // ma on s1: needs m1, m2 (s1-ordered) and v (evV)
        cudaStreamWaitEvent(s1, evV, 0);
        k_ma_s<<<NPIX/64, 256, 0, s1>>>(mm_dw, mm_dwb);
        cudaEventRecord(evM, s1);

        // join
        cudaStreamWaitEvent(0, evM, 0);
        cudaStreamWaitEvent(0, evP, 0);
        k_mv_b<<<NPIX/128, 256>>>(pvm, pwf, bp, pt2, out, 1);
    } else {
        k_fold16<<<16, 256>>>(mm_w1, mm_b1, mm_w2, mm_b2);
        k_gram_part<<<NCHUNK, 256>>>(x_in);
        k_gram_red1<<<(32*4096)/256, 256>>>();
        k_small4<<<BN, 256, SM4_BYTES>>>(Wq, Wk, Wp, rescale);
        k_mv_dual<<<NPIX/128, 512>>>(mask, mm_w1, mm_b1);
        k_mv_b<<<NPIX/128, 256>>>(x_in, Wv, nullptr, nullptr, pv, 0);
        k_pe1_s<<<NPIX/64, 256>>>(x_in, pe_w1);
        k_pe2_s<<<NPIX/64, 256>>>(pe_w2);
        k_ma_s <<<NPIX/64, 256>>>(mm_dw, mm_dwb);
        k_mv_b<<<NPIX/128, 256>>>(pvm, pwf, bp, pt2, out, 1);
    }
}